// round 1
// baseline (speedup 1.0000x reference)
#include <cuda_runtime.h>
#include <cstdint>

#define S_LEN   2048
#define HID     1024
#define NHEAD   16
#define HDIM    64
#define NBATCH  2
#define M_ROWS  (NBATCH * S_LEN)      // 4096
#define BH      (NBATCH * NHEAD)      // 32

// Scratch: Q and V in [B,H,S,d] layout (16 MB each)
__device__ float g_Q[(size_t)BH * S_LEN * HDIM];
__device__ float g_V[(size_t)BH * S_LEN * HDIM];

// ---------------------------------------------------------------------------
// Projection GEMM: C[M=4096, N=1024] = hidden @ W + bias, scattered into
// [B,H,S,d] layout. blockIdx.z selects (W_q,b_q)->g_Q or (W_v,b_v)->g_V.
// Classic 128x128x8 SGEMM, 256 threads, 8x8 per-thread tile.
// ---------------------------------------------------------------------------
#define BM 128
#define BN 128
#define BK 8

__global__ __launch_bounds__(256, 2)
void proj_gemm(const float* __restrict__ A,
               const float* __restrict__ Wq, const float* __restrict__ bq,
               const float* __restrict__ Wv, const float* __restrict__ bv)
{
    __shared__ float As[BK][BM];
    __shared__ float Bs[BK][BN];

    const float* W    = (blockIdx.z == 0) ? Wq : Wv;
    const float* bias = (blockIdx.z == 0) ? bq : bv;
    float*       Out  = (blockIdx.z == 0) ? g_Q : g_V;

    const int m0 = blockIdx.y * BM;
    const int n0 = blockIdx.x * BN;
    const int tid = threadIdx.x;

    const int arow = tid >> 1;           // 0..127
    const int acol = (tid & 1) * 4;      // 0 or 4
    const int brow = tid >> 5;           // 0..7
    const int bcol = (tid & 31) * 4;     // 0..124

    const int ty = tid >> 4;             // 0..15
    const int tx = tid & 15;             // 0..15

    float acc[8][8];
#pragma unroll
    for (int a = 0; a < 8; a++)
#pragma unroll
        for (int c = 0; c < 8; c++) acc[a][c] = 0.f;

    for (int k0 = 0; k0 < HID; k0 += BK) {
        float4 a4 = *(const float4*)&A[(size_t)(m0 + arow) * HID + k0 + acol];
        As[acol + 0][arow] = a4.x;
        As[acol + 1][arow] = a4.y;
        As[acol + 2][arow] = a4.z;
        As[acol + 3][arow] = a4.w;
        float4 b4 = *(const float4*)&W[(size_t)(k0 + brow) * HID + n0 + bcol];
        *(float4*)&Bs[brow][bcol] = b4;
        __syncthreads();

#pragma unroll
        for (int k = 0; k < BK; k++) {
            float4 ra0 = *(const float4*)&As[k][ty * 8];
            float4 ra1 = *(const float4*)&As[k][ty * 8 + 4];
            float4 rb0 = *(const float4*)&Bs[k][tx * 8];
            float4 rb1 = *(const float4*)&Bs[k][tx * 8 + 4];
            float ra[8] = {ra0.x, ra0.y, ra0.z, ra0.w, ra1.x, ra1.y, ra1.z, ra1.w};
            float rb[8] = {rb0.x, rb0.y, rb0.z, rb0.w, rb1.x, rb1.y, rb1.z, rb1.w};
#pragma unroll
            for (int a = 0; a < 8; a++)
#pragma unroll
                for (int c = 0; c < 8; c++)
                    acc[a][c] += ra[a] * rb[c];
        }
        __syncthreads();
    }

    // bias for this thread's 8 columns
    float bv8[8];
    const int nbase = n0 + tx * 8;
#pragma unroll
    for (int c = 0; c < 8; c++) bv8[c] = bias[nbase + c];

    const int h  = nbase >> 6;     // 8 | 64, so all 8 cols share a head
    const int dd = nbase & 63;

#pragma unroll
    for (int a = 0; a < 8; a++) {
        int m    = m0 + ty * 8 + a;
        int bb   = m >> 11;        // batch
        int srow = m & (S_LEN - 1);
        float* dst = &Out[((size_t)((bb * NHEAD + h) * S_LEN + srow)) * HDIM + dd];
        float4 v0 = {acc[a][0] + bv8[0], acc[a][1] + bv8[1],
                     acc[a][2] + bv8[2], acc[a][3] + bv8[3]};
        float4 v1 = {acc[a][4] + bv8[4], acc[a][5] + bv8[5],
                     acc[a][6] + bv8[6], acc[a][7] + bv8[7]};
        *(float4*)dst       = v0;
        *(float4*)(dst + 4) = v1;
    }
}

// ---------------------------------------------------------------------------
// Sparse strided attention.
// Masked logits are <= -1249 below row max => expf == 0.0f exactly, identical
// to reference softmax. Only compute allowed keys:
//   local window: j in [max(0, i-127), i]          (<=128 keys)
//   strided:      j = (i mod 128) + 128*k < i-127  (<=15 keys, from L2)
// One CTA = 128 queries of one (b,h). 256-row Q/V window in smem (stride 66).
// Warp w handles queries i0 + w + 8*t, t=0..15. Scores live in registers
// (5 per lane), warp-shuffle softmax, then PV accumulation.
// ---------------------------------------------------------------------------
#define QTILE 128
#define WSTRIDE 66
#define ATTN_SMEM (2 * 256 * WSTRIDE * 4)

__global__ __launch_bounds__(256)
void attn_kernel(const float* __restrict__ am, float* __restrict__ out)
{
    extern __shared__ float sm[];
    float* Qw = sm;
    float* Vw = sm + 256 * WSTRIDE;

    const int i0 = blockIdx.x * QTILE;
    const int bh = blockIdx.y;
    const int b  = bh >> 4;
    const int h  = bh & 15;

    const float* Qg  = g_Q + (size_t)bh * S_LEN * HDIM;
    const float* Vg  = g_V + (size_t)bh * S_LEN * HDIM;
    const float* amb = am + (size_t)b * S_LEN;

    const int j0  = (i0 >= QTILE) ? (i0 - QTILE) : 0;
    const int Wn  = (i0 + QTILE) - j0;          // 128 or 256

    const int tid = threadIdx.x;
    for (int idx = tid; idx < Wn * HDIM; idx += 256) {
        int r = idx >> 6, d = idx & 63;
        Qw[r * WSTRIDE + d] = Qg[(size_t)(j0 + r) * HDIM + d];
        Vw[r * WSTRIDE + d] = Vg[(size_t)(j0 + r) * HDIM + d];
    }
    __syncthreads();

    const int w    = tid >> 5;
    const int lane = tid & 31;
    const int cs   = i0 >> 7;                   // strided key count

    for (int t16 = 0; t16 < 16; t16++) {
        const int i   = i0 + w + 8 * t16;
        const int r   = i & (QTILE - 1);
        const int ri  = i - j0;
        const int cl  = min(QTILE, i + 1);
        const int nk  = cs + cl;
        const int jl0 = i - cl + 1;             // first local key

        const float2* qi2 = (const float2*)&Qw[ri * WSTRIDE];

        float sc[5];
#pragma unroll
        for (int u = 0; u < 5; u++) sc[u] = -1e30f;

#pragma unroll
        for (int u = 0; u < 5; u++) {
            int t = lane + u * 32;
            if (t < nk) {
                float s = 0.f;
                int j;
                if (t < cs) {
                    j = r + (t << 7);
                    const float2* qj2 = (const float2*)&Qg[(size_t)j * HDIM];
#pragma unroll
                    for (int d = 0; d < 32; d++) {
                        float2 a = qi2[d], qb = qj2[d];
                        s += a.x * qb.x + a.y * qb.y;
                    }
                } else {
                    j = jl0 + (t - cs);
                    const float2* qj2 = (const float2*)&Qw[(j - j0) * WSTRIDE];
#pragma unroll
                    for (int d = 0; d < 32; d++) {
                        float2 a = qi2[d], qb = qj2[d];
                        s += a.x * qb.x + a.y * qb.y;
                    }
                }
                sc[u] = s * 0.125f + amb[j];
            }
        }

        // warp softmax
        float mx = sc[0];
#pragma unroll
        for (int u = 1; u < 5; u++) mx = fmaxf(mx, sc[u]);
#pragma unroll
        for (int o = 16; o; o >>= 1) mx = fmaxf(mx, __shfl_xor_sync(0xFFFFFFFFu, mx, o));

        float p[5];
        float sum = 0.f;
#pragma unroll
        for (int u = 0; u < 5; u++) {
            p[u] = __expf(sc[u] - mx);          // invalid lanes: exp(-1e30) = 0
            sum += p[u];
        }
#pragma unroll
        for (int o = 16; o; o >>= 1) sum += __shfl_xor_sync(0xFFFFFFFFu, sum, o);
        const float inv = 1.0f / sum;

        // PV
        float c0 = 0.f, c1 = 0.f;
#pragma unroll
        for (int u = 0; u < 5; u++) {
            const int tbase = u * 32;
            if (tbase < nk) {
                const int cnt = min(32, nk - tbase);
                const float pu = p[u] * inv;
                for (int tt = 0; tt < cnt; tt++) {
                    float pt = __shfl_sync(0xFFFFFFFFu, pu, tt);
                    int t = tbase + tt;
                    const float* vrow;
                    if (t < cs) vrow = &Vg[(size_t)(r + (t << 7)) * HDIM];
                    else        vrow = &Vw[(jl0 + t - cs - j0) * WSTRIDE];
                    c0 += pt * vrow[lane];
                    c1 += pt * vrow[lane + 32];
                }
            }
        }

        float* o = &out[((size_t)(b * S_LEN + i)) * HID + h * HDIM];
        o[lane]      = c0;
        o[lane + 32] = c1;
    }
}

// ---------------------------------------------------------------------------
extern "C" void kernel_launch(void* const* d_in, const int* in_sizes, int n_in,
                              void* d_out, int out_size)
{
    const float* hidden = (const float*)d_in[0];
    const float* am     = (const float*)d_in[1];
    const float* Wq     = (const float*)d_in[2];
    const float* bq     = (const float*)d_in[3];
    const float* Wv     = (const float*)d_in[4];
    const float* bv     = (const float*)d_in[5];
    float* out = (float*)d_out;

    (void)in_sizes; (void)n_in; (void)out_size;

    cudaFuncSetAttribute(attn_kernel,
                         cudaFuncAttributeMaxDynamicSharedMemorySize, ATTN_SMEM);

    dim3 gg(HID / BN, M_ROWS / BM, 2);
    proj_gemm<<<gg, 256>>>(hidden, Wq, bq, Wv, bv);

    dim3 ga(S_LEN / QTILE, BH);
    attn_kernel<<<ga, 256, ATTN_SMEM>>>(am, out);
}

// round 2
// speedup vs baseline: 2.0900x; 2.0900x over previous
#include <cuda_runtime.h>
#include <cstdint>

#define S_LEN   2048
#define HID     1024
#define NHEAD   16
#define HDIM    64
#define NBATCH  2
#define M_ROWS  (NBATCH * S_LEN)      // 4096
#define BH      (NBATCH * NHEAD)      // 32

// Scratch: Q and V in [B,H,S,d] layout
__device__ float g_Q[(size_t)BH * S_LEN * HDIM];
__device__ float g_V[(size_t)BH * S_LEN * HDIM];

// ---------------------------------------------------------------------------
// Projection GEMM (unchanged from R1: ~40 TF/s fp32, near FFMA ceiling)
// ---------------------------------------------------------------------------
#define BM 128
#define BN 128
#define BK 8

__global__ __launch_bounds__(256, 2)
void proj_gemm(const float* __restrict__ A,
               const float* __restrict__ Wq, const float* __restrict__ bq,
               const float* __restrict__ Wv, const float* __restrict__ bv)
{
    __shared__ float As[BK][BM];
    __shared__ float Bs[BK][BN];

    const float* W    = (blockIdx.z == 0) ? Wq : Wv;
    const float* bias = (blockIdx.z == 0) ? bq : bv;
    float*       Out  = (blockIdx.z == 0) ? g_Q : g_V;

    const int m0 = blockIdx.y * BM;
    const int n0 = blockIdx.x * BN;
    const int tid = threadIdx.x;

    const int arow = tid >> 1;
    const int acol = (tid & 1) * 4;
    const int brow = tid >> 5;
    const int bcol = (tid & 31) * 4;

    const int ty = tid >> 4;
    const int tx = tid & 15;

    float acc[8][8];
#pragma unroll
    for (int a = 0; a < 8; a++)
#pragma unroll
        for (int c = 0; c < 8; c++) acc[a][c] = 0.f;

    for (int k0 = 0; k0 < HID; k0 += BK) {
        float4 a4 = *(const float4*)&A[(size_t)(m0 + arow) * HID + k0 + acol];
        As[acol + 0][arow] = a4.x;
        As[acol + 1][arow] = a4.y;
        As[acol + 2][arow] = a4.z;
        As[acol + 3][arow] = a4.w;
        float4 b4 = *(const float4*)&W[(size_t)(k0 + brow) * HID + n0 + bcol];
        *(float4*)&Bs[brow][bcol] = b4;
        __syncthreads();

#pragma unroll
        for (int k = 0; k < BK; k++) {
            float4 ra0 = *(const float4*)&As[k][ty * 8];
            float4 ra1 = *(const float4*)&As[k][ty * 8 + 4];
            float4 rb0 = *(const float4*)&Bs[k][tx * 8];
            float4 rb1 = *(const float4*)&Bs[k][tx * 8 + 4];
            float ra[8] = {ra0.x, ra0.y, ra0.z, ra0.w, ra1.x, ra1.y, ra1.z, ra1.w};
            float rb[8] = {rb0.x, rb0.y, rb0.z, rb0.w, rb1.x, rb1.y, rb1.z, rb1.w};
#pragma unroll
            for (int a = 0; a < 8; a++)
#pragma unroll
                for (int c = 0; c < 8; c++)
                    acc[a][c] += ra[a] * rb[c];
        }
        __syncthreads();
    }

    float bv8[8];
    const int nbase = n0 + tx * 8;
#pragma unroll
    for (int c = 0; c < 8; c++) bv8[c] = bias[nbase + c];

    const int h  = nbase >> 6;
    const int dd = nbase & 63;

#pragma unroll
    for (int a = 0; a < 8; a++) {
        int m    = m0 + ty * 8 + a;
        int bb   = m >> 11;
        int srow = m & (S_LEN - 1);
        float* dst = &Out[((size_t)((bb * NHEAD + h) * S_LEN + srow)) * HDIM + dd];
        float4 v0 = {acc[a][0] + bv8[0], acc[a][1] + bv8[1],
                     acc[a][2] + bv8[2], acc[a][3] + bv8[3]};
        float4 v1 = {acc[a][4] + bv8[4], acc[a][5] + bv8[5],
                     acc[a][6] + bv8[6], acc[a][7] + bv8[7]};
        *(float4*)dst       = v0;
        *(float4*)(dst + 4) = v1;
    }
}

// ---------------------------------------------------------------------------
// Attention v2: tile-dense register-blocked formulation.
//
// Query tile [i0, i0+128), window rows [j0, i0+128) with j0 = max(0, i0-128).
// In-window allowed: diff = i-j in [0, 128]  (local band + the m=1 stride key).
// Out-of-window strided keys: j = r + 128k, k < nstr = i0/128 - 1  -> diagonal
// per 128-block -> elementwise row-dot / row-axpy.
//
// Phases: [0] Q window -> smem d-major  [A] band-tile dense S-GEMM (8x8 reg
// tiles, masked tiles skipped)  [B] strided row-dots  [C] per-row softmax,
// p written in place (masked -> exact 0, matching fp32 underflow of ref),
// 1/sum deferred  [D] PV dense GEMM over live band cols + strided axpy,
// scaled epilogue.
// ---------------------------------------------------------------------------
#define QT      128
#define PPITCH  260
#define VPITCH  68
#define QV_FLOATS 17408          // max(64*260, 256*68)
#define ATTN_SMEM_FLOATS (128*PPITCH + QV_FLOATS + 16*128 + 128)
#define ATTN_SMEM (ATTN_SMEM_FLOATS * 4)

__global__ __launch_bounds__(512, 1)
void attn_kernel(const float* __restrict__ am, float* __restrict__ out)
{
    extern __shared__ float sm[];
    float* P    = sm;                       // [128][PPITCH]
    float* QV   = sm + 128 * PPITCH;        // Qd[64][PPITCH] then Vs[256][VPITCH]
    float* sstr = QV + QV_FLOATS;           // [16][128]
    float* sinv = sstr + 16 * 128;          // [128]

    const int i0 = blockIdx.x * QT;
    const int bh = blockIdx.y;
    const int b  = bh >> 4;
    const int h  = bh & 15;

    const float* Qg  = g_Q + (size_t)bh * S_LEN * HDIM;
    const float* Vg  = g_V + (size_t)bh * S_LEN * HDIM;
    const float* amb = am + (size_t)b * S_LEN;

    const int j0   = (i0 >= QT) ? (i0 - QT) : 0;
    const int Wn   = i0 + QT - j0;          // 128 or 256
    const int qoff = i0 - j0;               // 0 or 128
    const int nstr = (i0 >= 2 * QT) ? (i0 / QT - 1) : 0;

    const int tid = threadIdx.x;

    // ---- phase 0: Q window into smem, d-major ----
    float* Qd = QV;
    for (int idx = tid; idx < Wn * HDIM; idx += 512) {
        int c = idx >> 6, d = idx & 63;
        Qd[d * PPITCH + c] = Qg[(size_t)(j0 + c) * HDIM + d];
    }
    __syncthreads();

    const int ty = tid >> 5;                // 0..15 (warp id)
    const int tx = tid & 31;                // lane
    const int r0 = ty * 8;
    const int c0 = tx * 8;

    // ---- phase A: dense band scores ----
    {
        const bool active = (c0 < Wn) &&
                            (c0 + 7 >= qoff + r0 - 128) &&
                            (c0     <= qoff + r0 + 7);
        if (active) {
            float acc[8][8];
#pragma unroll
            for (int a = 0; a < 8; a++)
#pragma unroll
                for (int c = 0; c < 8; c++) acc[a][c] = 0.f;

#pragma unroll 8
            for (int d = 0; d < 64; d++) {
                const float* row = &Qd[d * PPITCH];
                float4 a0 = *(const float4*)&row[qoff + r0];
                float4 a1 = *(const float4*)&row[qoff + r0 + 4];
                float4 b0 = *(const float4*)&row[c0];
                float4 b1 = *(const float4*)&row[c0 + 4];
                float ra[8] = {a0.x, a0.y, a0.z, a0.w, a1.x, a1.y, a1.z, a1.w};
                float rb[8] = {b0.x, b0.y, b0.z, b0.w, b1.x, b1.y, b1.z, b1.w};
#pragma unroll
                for (int a = 0; a < 8; a++)
#pragma unroll
                    for (int c = 0; c < 8; c++)
                        acc[a][c] += ra[a] * rb[c];
            }
            float am8[8];
#pragma unroll
            for (int c = 0; c < 8; c++) am8[c] = amb[j0 + c0 + c];
#pragma unroll
            for (int a = 0; a < 8; a++) {
                float4 v0 = {acc[a][0] * 0.125f + am8[0], acc[a][1] * 0.125f + am8[1],
                             acc[a][2] * 0.125f + am8[2], acc[a][3] * 0.125f + am8[3]};
                float4 v1 = {acc[a][4] * 0.125f + am8[4], acc[a][5] * 0.125f + am8[5],
                             acc[a][6] * 0.125f + am8[6], acc[a][7] * 0.125f + am8[7]};
                float* dst = &P[(r0 + a) * PPITCH + c0];
                *(float4*)dst       = v0;
                *(float4*)(dst + 4) = v1;
            }
        }
    }

    // ---- phase B: strided row-dots (diagonal of each 128-block) ----
    const int rB = tid >> 2;                // 0..127
    const int qB = tid & 3;                 // 0..3
    {
        const int qc = qoff + rB;
        for (int k = 0; k < nstr; k++) {
            int jb = k * QT + rB;
            const float* qrow = &Qg[(size_t)jb * HDIM];
            float s = 0.f;
#pragma unroll
            for (int it = 0; it < 16; it++) {
                int d = qB + it * 4;
                s += Qd[d * PPITCH + qc] * qrow[d];
            }
            s += __shfl_xor_sync(0xFFFFFFFFu, s, 1);
            s += __shfl_xor_sync(0xFFFFFFFFu, s, 2);
            if (qB == 0) sstr[k * 128 + rB] = s * 0.125f + amb[jb];
        }
    }
    __syncthreads();

    // ---- phase C: softmax (p in place, masked -> 0, 1/sum deferred) ----
    {
        const int r   = rB;
        const int clo = max(0, qoff + r - 128);
        const int chi = qoff + r;
        const float* Pr = &P[r * PPITCH];
        float* Pw = &P[r * PPITCH];

        float mx = -1e30f;
        for (int c = clo + qB; c <= chi; c += 4) mx = fmaxf(mx, Pr[c]);
        for (int k = qB; k < nstr; k += 4)       mx = fmaxf(mx, sstr[k * 128 + r]);
        mx = fmaxf(mx, __shfl_xor_sync(0xFFFFFFFFu, mx, 1));
        mx = fmaxf(mx, __shfl_xor_sync(0xFFFFFFFFu, mx, 2));

        float sum = 0.f;
        for (int c = qB; c < Wn; c += 4) {
            float v = Pr[c];
            float p = (c >= clo && c <= chi) ? __expf(v - mx) : 0.f;
            Pw[c] = p;
            sum += p;
        }
        for (int k = qB; k < nstr; k += 4) {
            float p = __expf(sstr[k * 128 + r] - mx);
            sstr[k * 128 + r] = p;
            sum += p;
        }
        sum += __shfl_xor_sync(0xFFFFFFFFu, sum, 1);
        sum += __shfl_xor_sync(0xFFFFFFFFu, sum, 2);
        if (qB == 0) sinv[r] = 1.0f / sum;
    }

    // ---- load V window (over dead Qd region) ----
    float* Vs = QV;
    for (int idx = tid; idx < Wn * HDIM; idx += 512) {
        int c = idx >> 6, d = idx & 63;
        Vs[c * VPITCH + d] = Vg[(size_t)(j0 + c) * HDIM + d];
    }
    __syncthreads();

    // ---- phase D: PV over live band + strided axpy, scaled epilogue ----
    {
        const int d0 = tx * 2;
        float cx[8], cy[8];
#pragma unroll
        for (int a = 0; a < 8; a++) { cx[a] = 0.f; cy[a] = 0.f; }

        const int cloW = max(0, qoff + r0 - 128);
        const int chiW = qoff + r0 + 7;     // <= Wn-1 always
        for (int c = cloW; c <= chiW; c++) {
            float2 v = *(const float2*)&Vs[c * VPITCH + d0];
#pragma unroll
            for (int a = 0; a < 8; a++) {
                float p = P[(r0 + a) * PPITCH + c];
                cx[a] += p * v.x;
                cy[a] += p * v.y;
            }
        }
        for (int k = 0; k < nstr; k++) {
#pragma unroll
            for (int a = 0; a < 8; a++) {
                int r = r0 + a;
                float p = sstr[k * 128 + r];
                float2 v = *(const float2*)&Vg[(size_t)(k * QT + r) * HDIM + d0];
                cx[a] += p * v.x;
                cy[a] += p * v.y;
            }
        }
#pragma unroll
        for (int a = 0; a < 8; a++) {
            int r = r0 + a;
            float inv = sinv[r];
            int i = i0 + r;
            float2 o2 = {cx[a] * inv, cy[a] * inv};
            *(float2*)&out[((size_t)(b * S_LEN + i)) * HID + h * HDIM + d0] = o2;
        }
    }
}

// ---------------------------------------------------------------------------
extern "C" void kernel_launch(void* const* d_in, const int* in_sizes, int n_in,
                              void* d_out, int out_size)
{
    const float* hidden = (const float*)d_in[0];
    const float* am     = (const float*)d_in[1];
    const float* Wq     = (const float*)d_in[2];
    const float* bq     = (const float*)d_in[3];
    const float* Wv     = (const float*)d_in[4];
    const float* bv     = (const float*)d_in[5];
    float* out = (float*)d_out;

    (void)in_sizes; (void)n_in; (void)out_size;

    cudaFuncSetAttribute(attn_kernel,
                         cudaFuncAttributeMaxDynamicSharedMemorySize, ATTN_SMEM);

    dim3 gg(HID / BN, M_ROWS / BM, 2);
    proj_gemm<<<gg, 256>>>(hidden, Wq, bq, Wv, bv);

    dim3 ga(S_LEN / QT, BH);
    attn_kernel<<<ga, 512, ATTN_SMEM>>>(am, out);
}

// round 5
// speedup vs baseline: 4.3512x; 2.0819x over previous
#include <cuda_runtime.h>
#include <cstdint>

#define S_LEN   2048
#define HID     1024
#define NHEAD   16
#define HDIM    64
#define NBATCH  2
#define M_ROWS  (NBATCH * S_LEN)      // 4096
#define BH      (NBATCH * NHEAD)      // 32

// Scratch (device globals; ONLY referenced from device code)
__device__ float g_Q[(size_t)BH * S_LEN * HDIM];
__device__ float g_V[(size_t)BH * S_LEN * HDIM];
__device__ float g_At[(size_t)M_ROWS * HID];        // tf32-rounded hidden
__device__ float g_Wt[2 * (size_t)HID * HID];       // tf32-rounded Wq, Wv

// ---------------------------------------------------------------------------
// tf32 round pre-passes (cvt.rna = round-to-nearest). Destinations are the
// device globals, addressed from DEVICE code (host must not touch symbols).
// ---------------------------------------------------------------------------
__device__ __forceinline__ uint4 rna4(float4 v) {
    uint4 u;
    asm("cvt.rna.tf32.f32 %0, %1;" : "=r"(u.x) : "f"(v.x));
    asm("cvt.rna.tf32.f32 %0, %1;" : "=r"(u.y) : "f"(v.y));
    asm("cvt.rna.tf32.f32 %0, %1;" : "=r"(u.z) : "f"(v.z));
    asm("cvt.rna.tf32.f32 %0, %1;" : "=r"(u.w) : "f"(v.w));
    return u;
}

__global__ void conv_A_tf32(const float* __restrict__ src)
{
    size_t i = (size_t)blockIdx.x * blockDim.x + threadIdx.x;
    ((uint4*)g_At)[i] = rna4(((const float4*)src)[i]);
}

__global__ void conv_W_tf32(const float* __restrict__ Wq,
                            const float* __restrict__ Wv)
{
    const int z = blockIdx.y;
    const float* src = z ? Wv : Wq;
    float* dst = g_Wt + (size_t)z * HID * HID;
    size_t i = (size_t)blockIdx.x * blockDim.x + threadIdx.x;
    ((uint4*)dst)[i] = rna4(((const float4*)src)[i]);
}

// ---------------------------------------------------------------------------
// tf32 mma.sync projection GEMM.
// C[4096,1024] = At @ Wt(z) + bias(z), scattered to [B,H,S,d].
// CTA: 128x128 tile, 256 threads (8 warps, 2x4), warp tile 64x32
// (4 m16 x 4 n8 mma tiles). K in 32 stages of 32, cp.async double buffer.
// ---------------------------------------------------------------------------
#define BKG 32
#define APITCH 36
#define BPITCH 136
#define ABUF (128 * APITCH)
#define BBUF (32 * BPITCH)
#define PROJ_SMEM ((2 * ABUF + 2 * BBUF) * 4)       // 71680 B

__device__ __forceinline__ uint32_t smem_u32(const void* p) {
    uint32_t a;
    asm("{ .reg .u64 t; cvta.to.shared.u64 t, %1; cvt.u32.u64 %0, t; }"
        : "=r"(a) : "l"(p));
    return a;
}

#define CP16(dst, src) \
    asm volatile("cp.async.cg.shared.global [%0], [%1], 16;" \
                 :: "r"(dst), "l"(src) : "memory")
#define CP_COMMIT() asm volatile("cp.async.commit_group;" ::: "memory")
#define CP_WAIT1()  asm volatile("cp.async.wait_group 1;" ::: "memory")
#define CP_WAIT0()  asm volatile("cp.async.wait_group 0;" ::: "memory")

#define MMA_TF32(c, a0, a1, a2, a3, b0, b1)                                   \
    asm volatile("mma.sync.aligned.m16n8k8.row.col.f32.tf32.tf32.f32 "        \
        "{%0,%1,%2,%3}, {%4,%5,%6,%7}, {%8,%9}, {%0,%1,%2,%3};"               \
        : "+f"((c)[0]), "+f"((c)[1]), "+f"((c)[2]), "+f"((c)[3])              \
        : "r"(a0), "r"(a1), "r"(a2), "r"(a3), "r"(b0), "r"(b1))

__global__ __launch_bounds__(256)
void proj_mma(const float* __restrict__ bq, const float* __restrict__ bv)
{
    extern __shared__ float smp[];
    float* Asm = smp;                       // [2][128][APITCH]
    float* Bsm = smp + 2 * ABUF;            // [2][32][BPITCH]

    const int tid = threadIdx.x;
    const int z  = blockIdx.z;
    const int n0 = blockIdx.x * 128;
    const int m0 = blockIdx.y * 128;

    const float* Wg   = g_Wt + (size_t)z * HID * HID;
    const float* bias = z ? bv : bq;
    float*       Out  = z ? g_V : g_Q;

    const uint32_t sA = smem_u32(Asm);
    const uint32_t sB = smem_u32(Bsm);

    auto load_stage = [&](int s, int buf) {
        const int k0 = s * BKG;
        const uint32_t aB = sA + buf * ABUF * 4;
        const uint32_t bB = sB + buf * BBUF * 4;
#pragma unroll
        for (int it = 0; it < 4; it++) {
            int idx = tid + it * 256;
            int r = idx >> 3, c = idx & 7;
            CP16(aB + (r * APITCH + c * 4) * 4,
                 &g_At[(size_t)(m0 + r) * HID + k0 + c * 4]);
        }
#pragma unroll
        for (int it = 0; it < 4; it++) {
            int idx = tid + it * 256;
            int k = idx >> 5, c = idx & 31;
            CP16(bB + (k * BPITCH + c * 4) * 4,
                 &Wg[(size_t)(k0 + k) * HID + n0 + c * 4]);
        }
        CP_COMMIT();
    };

    const int wid = tid >> 5, lane = tid & 31;
    const int wm = (wid & 1) * 64;
    const int wn = (wid >> 1) * 32;
    const int lg = lane >> 2, lq = lane & 3;

    float acc[4][4][4];
#pragma unroll
    for (int mt = 0; mt < 4; mt++)
#pragma unroll
        for (int nt = 0; nt < 4; nt++)
#pragma unroll
            for (int e = 0; e < 4; e++) acc[mt][nt][e] = 0.f;

    auto compute_stage = [&](int buf) {
        const float* Ab = Asm + buf * ABUF;
        const float* Bb = Bsm + buf * BBUF;
#pragma unroll
        for (int ks = 0; ks < 4; ks++) {
            const int kb = ks * 8;
            uint32_t b0[4], b1[4];
#pragma unroll
            for (int nt = 0; nt < 4; nt++) {
                const int n = wn + nt * 8 + lg;
                b0[nt] = __float_as_uint(Bb[(kb + lq) * BPITCH + n]);
                b1[nt] = __float_as_uint(Bb[(kb + lq + 4) * BPITCH + n]);
            }
#pragma unroll
            for (int mt = 0; mt < 4; mt++) {
                const float* ar = Ab + (wm + mt * 16 + lg) * APITCH + kb + lq;
                uint32_t a0 = __float_as_uint(ar[0]);
                uint32_t a1 = __float_as_uint(ar[8 * APITCH]);
                uint32_t a2 = __float_as_uint(ar[4]);
                uint32_t a3 = __float_as_uint(ar[8 * APITCH + 4]);
#pragma unroll
                for (int nt = 0; nt < 4; nt++)
                    MMA_TF32(acc[mt][nt], a0, a1, a2, a3, b0[nt], b1[nt]);
            }
        }
    };

    load_stage(0, 0);
    load_stage(1, 1);
    const int NST = HID / BKG;              // 32
    for (int s = 0; s < NST; s++) {
        if (s < NST - 1) CP_WAIT1(); else CP_WAIT0();
        __syncthreads();
        compute_stage(s & 1);
        __syncthreads();
        if (s + 2 < NST) load_stage(s + 2, s & 1);
    }

    // epilogue: + bias, scatter to [B,H,S,d]
#pragma unroll
    for (int mt = 0; mt < 4; mt++) {
        const int mA = m0 + wm + mt * 16 + lg;
        const int mB = mA + 8;
#pragma unroll
        for (int nt = 0; nt < 4; nt++) {
            const int n = n0 + wn + nt * 8 + lq * 2;
            const float2 b2 = *(const float2*)&bias[n];
            const int h = n >> 6, d = n & 63;
            {
                int bb = mA >> 11, sr = mA & (S_LEN - 1);
                float2 o = {acc[mt][nt][0] + b2.x, acc[mt][nt][1] + b2.y};
                *(float2*)&Out[((size_t)((bb * NHEAD + h) * S_LEN + sr)) * HDIM + d] = o;
            }
            {
                int bb = mB >> 11, sr = mB & (S_LEN - 1);
                float2 o = {acc[mt][nt][2] + b2.x, acc[mt][nt][3] + b2.y};
                *(float2*)&Out[((size_t)((bb * NHEAD + h) * S_LEN + sr)) * HDIM + d] = o;
            }
        }
    }
}

// ---------------------------------------------------------------------------
// Attention (unchanged from R2: tile-dense sparse formulation, 166us)
// ---------------------------------------------------------------------------
#define QT      128
#define PPITCH  260
#define VPITCH  68
#define QV_FLOATS 17408
#define ATTN_SMEM_FLOATS (128*PPITCH + QV_FLOATS + 16*128 + 128)
#define ATTN_SMEM (ATTN_SMEM_FLOATS * 4)

__global__ __launch_bounds__(512, 1)
void attn_kernel(const float* __restrict__ am, float* __restrict__ out)
{
    extern __shared__ float sm[];
    float* P    = sm;
    float* QV   = sm + 128 * PPITCH;
    float* sstr = QV + QV_FLOATS;
    float* sinv = sstr + 16 * 128;

    const int i0 = blockIdx.x * QT;
    const int bh = blockIdx.y;
    const int b  = bh >> 4;
    const int h  = bh & 15;

    const float* Qg  = g_Q + (size_t)bh * S_LEN * HDIM;
    const float* Vg  = g_V + (size_t)bh * S_LEN * HDIM;
    const float* amb = am + (size_t)b * S_LEN;

    const int j0   = (i0 >= QT) ? (i0 - QT) : 0;
    const int Wn   = i0 + QT - j0;
    const int qoff = i0 - j0;
    const int nstr = (i0 >= 2 * QT) ? (i0 / QT - 1) : 0;

    const int tid = threadIdx.x;

    float* Qd = QV;
    for (int idx = tid; idx < Wn * HDIM; idx += 512) {
        int c = idx >> 6, d = idx & 63;
        Qd[d * PPITCH + c] = Qg[(size_t)(j0 + c) * HDIM + d];
    }
    __syncthreads();

    const int ty = tid >> 5;
    const int tx = tid & 31;
    const int r0 = ty * 8;
    const int c0 = tx * 8;

    {
        const bool active = (c0 < Wn) &&
                            (c0 + 7 >= qoff + r0 - 128) &&
                            (c0     <= qoff + r0 + 7);
        if (active) {
            float acc[8][8];
#pragma unroll
            for (int a = 0; a < 8; a++)
#pragma unroll
                for (int c = 0; c < 8; c++) acc[a][c] = 0.f;

#pragma unroll 8
            for (int d = 0; d < 64; d++) {
                const float* row = &Qd[d * PPITCH];
                float4 a0 = *(const float4*)&row[qoff + r0];
                float4 a1 = *(const float4*)&row[qoff + r0 + 4];
                float4 b0 = *(const float4*)&row[c0];
                float4 b1 = *(const float4*)&row[c0 + 4];
                float ra[8] = {a0.x, a0.y, a0.z, a0.w, a1.x, a1.y, a1.z, a1.w};
                float rb[8] = {b0.x, b0.y, b0.z, b0.w, b1.x, b1.y, b1.z, b1.w};
#pragma unroll
                for (int a = 0; a < 8; a++)
#pragma unroll
                    for (int c = 0; c < 8; c++)
                        acc[a][c] += ra[a] * rb[c];
            }
            float am8[8];
#pragma unroll
            for (int c = 0; c < 8; c++) am8[c] = amb[j0 + c0 + c];
#pragma unroll
            for (int a = 0; a < 8; a++) {
                float4 v0 = {acc[a][0] * 0.125f + am8[0], acc[a][1] * 0.125f + am8[1],
                             acc[a][2] * 0.125f + am8[2], acc[a][3] * 0.125f + am8[3]};
                float4 v1 = {acc[a][4] * 0.125f + am8[4], acc[a][5] * 0.125f + am8[5],
                             acc[a][6] * 0.125f + am8[6], acc[a][7] * 0.125f + am8[7]};
                float* dst = &P[(r0 + a) * PPITCH + c0];
                *(float4*)dst       = v0;
                *(float4*)(dst + 4) = v1;
            }
        }
    }

    const int rB = tid >> 2;
    const int qB = tid & 3;
    {
        const int qc = qoff + rB;
        for (int k = 0; k < nstr; k++) {
            int jb = k * QT + rB;
            const float* qrow = &Qg[(size_t)jb * HDIM];
            float s = 0.f;
#pragma unroll
            for (int it = 0; it < 16; it++) {
                int d = qB + it * 4;
                s += Qd[d * PPITCH + qc] * qrow[d];
            }
            s += __shfl_xor_sync(0xFFFFFFFFu, s, 1);
            s += __shfl_xor_sync(0xFFFFFFFFu, s, 2);
            if (qB == 0) sstr[k * 128 + rB] = s * 0.125f + amb[jb];
        }
    }
    __syncthreads();

    {
        const int r   = rB;
        const int clo = max(0, qoff + r - 128);
        const int chi = qoff + r;
        const float* Pr = &P[r * PPITCH];
        float* Pw = &P[r * PPITCH];

        float mx = -1e30f;
        for (int c = clo + qB; c <= chi; c += 4) mx = fmaxf(mx, Pr[c]);
        for (int k = qB; k < nstr; k += 4)       mx = fmaxf(mx, sstr[k * 128 + r]);
        mx = fmaxf(mx, __shfl_xor_sync(0xFFFFFFFFu, mx, 1));
        mx = fmaxf(mx, __shfl_xor_sync(0xFFFFFFFFu, mx, 2));

        float sum = 0.f;
        for (int c = qB; c < Wn; c += 4) {
            float v = Pr[c];
            float p = (c >= clo && c <= chi) ? __expf(v - mx) : 0.f;
            Pw[c] = p;
            sum += p;
        }
        for (int k = qB; k < nstr; k += 4) {
            float p = __expf(sstr[k * 128 + r] - mx);
            sstr[k * 128 + r] = p;
            sum += p;
        }
        sum += __shfl_xor_sync(0xFFFFFFFFu, sum, 1);
        sum += __shfl_xor_sync(0xFFFFFFFFu, sum, 2);
        if (qB == 0) sinv[r] = 1.0f / sum;
    }

    float* Vs = QV;
    for (int idx = tid; idx < Wn * HDIM; idx += 512) {
        int c = idx >> 6, d = idx & 63;
        Vs[c * VPITCH + d] = Vg[(size_t)(j0 + c) * HDIM + d];
    }
    __syncthreads();

    {
        const int d0 = tx * 2;
        float cx[8], cy[8];
#pragma unroll
        for (int a = 0; a < 8; a++) { cx[a] = 0.f; cy[a] = 0.f; }

        const int cloW = max(0, qoff + r0 - 128);
        const int chiW = qoff + r0 + 7;
        for (int c = cloW; c <= chiW; c++) {
            float2 v = *(const float2*)&Vs[c * VPITCH + d0];
#pragma unroll
            for (int a = 0; a < 8; a++) {
                float p = P[(r0 + a) * PPITCH + c];
                cx[a] += p * v.x;
                cy[a] += p * v.y;
            }
        }
        for (int k = 0; k < nstr; k++) {
#pragma unroll
            for (int a = 0; a < 8; a++) {
                int r = r0 + a;
                float p = sstr[k * 128 + r];
                float2 v = *(const float2*)&Vg[(size_t)(k * QT + r) * HDIM + d0];
                cx[a] += p * v.x;
                cy[a] += p * v.y;
            }
        }
#pragma unroll
        for (int a = 0; a < 8; a++) {
            int r = r0 + a;
            float inv = sinv[r];
            int i = i0 + r;
            float2 o2 = {cx[a] * inv, cy[a] * inv};
            *(float2*)&out[((size_t)(b * S_LEN + i)) * HID + h * HDIM + d0] = o2;
        }
    }
}

// ---------------------------------------------------------------------------
extern "C" void kernel_launch(void* const* d_in, const int* in_sizes, int n_in,
                              void* d_out, int out_size)
{
    const float* hidden = (const float*)d_in[0];
    const float* am     = (const float*)d_in[1];
    const float* Wq     = (const float*)d_in[2];
    const float* bq     = (const float*)d_in[3];
    const float* Wv     = (const float*)d_in[4];
    const float* bv     = (const float*)d_in[5];
    float* out = (float*)d_out;

    (void)in_sizes; (void)n_in; (void)out_size;

    cudaFuncSetAttribute(proj_mma,
                         cudaFuncAttributeMaxDynamicSharedMemorySize, PROJ_SMEM);
    cudaFuncSetAttribute(attn_kernel,
                         cudaFuncAttributeMaxDynamicSharedMemorySize, ATTN_SMEM);

    // tf32 rounding pre-passes (device-symbol destinations addressed in-kernel)
    conv_A_tf32<<<(M_ROWS * HID / 4) / 256, 256>>>(hidden);
    dim3 gw((HID * HID / 4) / 256, 2);
    conv_W_tf32<<<gw, 256>>>(Wq, Wv);

    dim3 gp(HID / 128, M_ROWS / 128, 2);
    proj_mma<<<gp, 256, PROJ_SMEM>>>(bq, bv);

    dim3 ga(S_LEN / QT, BH);
    attn_kernel<<<ga, 512, ATTN_SMEM>>>(am, out);
}

// round 6
// speedup vs baseline: 5.2395x; 1.2042x over previous
#include <cuda_runtime.h>
#include <cstdint>

#define S_LEN   2048
#define HID     1024
#define NHEAD   16
#define HDIM    64
#define NBATCH  2
#define M_ROWS  (NBATCH * S_LEN)      // 4096
#define BH      (NBATCH * NHEAD)      // 32

// Scratch (device globals; ONLY referenced from device code)
__device__ float g_Q[(size_t)BH * S_LEN * HDIM];
__device__ float g_V[(size_t)BH * S_LEN * HDIM];
__device__ float g_At[(size_t)M_ROWS * HID];        // tf32-rounded hidden
__device__ float g_Wt[2 * (size_t)HID * HID];       // tf32-rounded Wq, Wv

// ---------------------------------------------------------------------------
// tf32 helpers
// ---------------------------------------------------------------------------
__device__ __forceinline__ uint4 rna4(float4 v) {
    uint4 u;
    asm("cvt.rna.tf32.f32 %0, %1;" : "=r"(u.x) : "f"(v.x));
    asm("cvt.rna.tf32.f32 %0, %1;" : "=r"(u.y) : "f"(v.y));
    asm("cvt.rna.tf32.f32 %0, %1;" : "=r"(u.z) : "f"(v.z));
    asm("cvt.rna.tf32.f32 %0, %1;" : "=r"(u.w) : "f"(v.w));
    return u;
}
__device__ __forceinline__ uint32_t rna1(float v) {
    uint32_t u;
    asm("cvt.rna.tf32.f32 %0, %1;" : "=r"(u) : "f"(v));
    return u;
}

__global__ void conv_A_tf32(const float* __restrict__ src)
{
    size_t i = (size_t)blockIdx.x * blockDim.x + threadIdx.x;
    ((uint4*)g_At)[i] = rna4(((const float4*)src)[i]);
}

__global__ void conv_W_tf32(const float* __restrict__ Wq,
                            const float* __restrict__ Wv)
{
    const int z = blockIdx.y;
    const float* src = z ? Wv : Wq;
    float* dst = g_Wt + (size_t)z * HID * HID;
    size_t i = (size_t)blockIdx.x * blockDim.x + threadIdx.x;
    ((uint4*)dst)[i] = rna4(((const float4*)src)[i]);
}

// ---------------------------------------------------------------------------
// tf32 mma.sync projection GEMM (unchanged from R5; near legacy-HMMA ceiling)
// ---------------------------------------------------------------------------
#define BKG 32
#define APITCH 36
#define BPITCH 136
#define ABUF (128 * APITCH)
#define BBUF (32 * BPITCH)
#define PROJ_SMEM ((2 * ABUF + 2 * BBUF) * 4)       // 71680 B

__device__ __forceinline__ uint32_t smem_u32(const void* p) {
    uint32_t a;
    asm("{ .reg .u64 t; cvta.to.shared.u64 t, %1; cvt.u32.u64 %0, t; }"
        : "=r"(a) : "l"(p));
    return a;
}

#define CP16(dst, src) \
    asm volatile("cp.async.cg.shared.global [%0], [%1], 16;" \
                 :: "r"(dst), "l"(src) : "memory")
#define CP_COMMIT() asm volatile("cp.async.commit_group;" ::: "memory")
#define CP_WAIT1()  asm volatile("cp.async.wait_group 1;" ::: "memory")
#define CP_WAIT0()  asm volatile("cp.async.wait_group 0;" ::: "memory")

#define MMA_TF32(c, a0, a1, a2, a3, b0, b1)                                   \
    asm volatile("mma.sync.aligned.m16n8k8.row.col.f32.tf32.tf32.f32 "        \
        "{%0,%1,%2,%3}, {%4,%5,%6,%7}, {%8,%9}, {%0,%1,%2,%3};"               \
        : "+f"((c)[0]), "+f"((c)[1]), "+f"((c)[2]), "+f"((c)[3])              \
        : "r"(a0), "r"(a1), "r"(a2), "r"(a3), "r"(b0), "r"(b1))

__global__ __launch_bounds__(256)
void proj_mma(const float* __restrict__ bq, const float* __restrict__ bv)
{
    extern __shared__ float smp[];
    float* Asm = smp;                       // [2][128][APITCH]
    float* Bsm = smp + 2 * ABUF;            // [2][32][BPITCH]

    const int tid = threadIdx.x;
    const int z  = blockIdx.z;
    const int n0 = blockIdx.x * 128;
    const int m0 = blockIdx.y * 128;

    const float* Wg   = g_Wt + (size_t)z * HID * HID;
    const float* bias = z ? bv : bq;
    float*       Out  = z ? g_V : g_Q;

    const uint32_t sA = smem_u32(Asm);
    const uint32_t sB = smem_u32(Bsm);

    auto load_stage = [&](int s, int buf) {
        const int k0 = s * BKG;
        const uint32_t aB = sA + buf * ABUF * 4;
        const uint32_t bB = sB + buf * BBUF * 4;
#pragma unroll
        for (int it = 0; it < 4; it++) {
            int idx = tid + it * 256;
            int r = idx >> 3, c = idx & 7;
            CP16(aB + (r * APITCH + c * 4) * 4,
                 &g_At[(size_t)(m0 + r) * HID + k0 + c * 4]);
        }
#pragma unroll
        for (int it = 0; it < 4; it++) {
            int idx = tid + it * 256;
            int k = idx >> 5, c = idx & 31;
            CP16(bB + (k * BPITCH + c * 4) * 4,
                 &Wg[(size_t)(k0 + k) * HID + n0 + c * 4]);
        }
        CP_COMMIT();
    };

    const int wid = tid >> 5, lane = tid & 31;
    const int wm = (wid & 1) * 64;
    const int wn = (wid >> 1) * 32;
    const int lg = lane >> 2, lq = lane & 3;

    float acc[4][4][4];
#pragma unroll
    for (int mt = 0; mt < 4; mt++)
#pragma unroll
        for (int nt = 0; nt < 4; nt++)
#pragma unroll
            for (int e = 0; e < 4; e++) acc[mt][nt][e] = 0.f;

    auto compute_stage = [&](int buf) {
        const float* Ab = Asm + buf * ABUF;
        const float* Bb = Bsm + buf * BBUF;
#pragma unroll
        for (int ks = 0; ks < 4; ks++) {
            const int kb = ks * 8;
            uint32_t b0[4], b1[4];
#pragma unroll
            for (int nt = 0; nt < 4; nt++) {
                const int n = wn + nt * 8 + lg;
                b0[nt] = __float_as_uint(Bb[(kb + lq) * BPITCH + n]);
                b1[nt] = __float_as_uint(Bb[(kb + lq + 4) * BPITCH + n]);
            }
#pragma unroll
            for (int mt = 0; mt < 4; mt++) {
                const float* ar = Ab + (wm + mt * 16 + lg) * APITCH + kb + lq;
                uint32_t a0 = __float_as_uint(ar[0]);
                uint32_t a1 = __float_as_uint(ar[8 * APITCH]);
                uint32_t a2 = __float_as_uint(ar[4]);
                uint32_t a3 = __float_as_uint(ar[8 * APITCH + 4]);
#pragma unroll
                for (int nt = 0; nt < 4; nt++)
                    MMA_TF32(acc[mt][nt], a0, a1, a2, a3, b0[nt], b1[nt]);
            }
        }
    };

    load_stage(0, 0);
    load_stage(1, 1);
    const int NST = HID / BKG;              // 32
    for (int s = 0; s < NST; s++) {
        if (s < NST - 1) CP_WAIT1(); else CP_WAIT0();
        __syncthreads();
        compute_stage(s & 1);
        __syncthreads();
        if (s + 2 < NST) load_stage(s + 2, s & 1);
    }

#pragma unroll
    for (int mt = 0; mt < 4; mt++) {
        const int mA = m0 + wm + mt * 16 + lg;
        const int mB = mA + 8;
#pragma unroll
        for (int nt = 0; nt < 4; nt++) {
            const int n = n0 + wn + nt * 8 + lq * 2;
            const float2 b2 = *(const float2*)&bias[n];
            const int h = n >> 6, d = n & 63;
            {
                int bb = mA >> 11, sr = mA & (S_LEN - 1);
                float2 o = {acc[mt][nt][0] + b2.x, acc[mt][nt][1] + b2.y};
                *(float2*)&Out[((size_t)((bb * NHEAD + h) * S_LEN + sr)) * HDIM + d] = o;
            }
            {
                int bb = mB >> 11, sr = mB & (S_LEN - 1);
                float2 o = {acc[mt][nt][2] + b2.x, acc[mt][nt][3] + b2.y};
                *(float2*)&Out[((size_t)((bb * NHEAD + h) * S_LEN + sr)) * HDIM + d] = o;
            }
        }
    }
}

// ---------------------------------------------------------------------------
// Attention v3: tf32 mma.sync for S and PV.
// CTA = 128 queries x one (b,h), 256 threads (8 warps), warp = 16 query rows.
// Live band per warp: 18 n8-tiles [t_lo, t_lo+18) with t_lo=(qoff+r0-128)/8
// (t >= 0 predicate; t < Wn/8 holds by construction). Strided diagonal keys
// (j = r + 128k, k < nstr) handled scalar. Softmax in c-fragment registers,
// p -> tf32 in P smem, masked -> exact 0, 1/sum deferred to epilogue.
// Smem pitches: Qs 68 / P 260 (=4 mod 32, row-g frag pattern), Vs 72
// (=8 mod 32, col-g frag pattern) -> conflict-free fragment LDS.
// ---------------------------------------------------------------------------
#define NT_S 18
#define QPITCH 68
#define VPITCH3 72
#define PPITCH3 260
#define QV3_FLOATS (256 * VPITCH3)          // 18432 (>= 256*QPITCH)
#define ATTN3_FLOATS (128 * PPITCH3 + QV3_FLOATS + 256 + 15 * 128)
#define ATTN3_SMEM (ATTN3_FLOATS * 4)       // 215552 B

__global__ __launch_bounds__(256, 1)
void attn_mma(const float* __restrict__ am, float* __restrict__ out)
{
    extern __shared__ float sm3[];
    float* P    = sm3;                        // [128][260]
    float* QV   = sm3 + 128 * PPITCH3;        // Qs[256][68] then Vs[256][72]
    float* ams  = QV + QV3_FLOATS;            // [256]
    float* sstr = ams + 256;                  // [15][128]

    const int i0 = blockIdx.x * 128;
    const int bh = blockIdx.y;
    const int b  = bh >> 4;
    const int h  = bh & 15;

    const float* Qg  = g_Q + (size_t)bh * S_LEN * HDIM;
    const float* Vg  = g_V + (size_t)bh * S_LEN * HDIM;
    const float* amb = am + (size_t)b * S_LEN;

    const int j0   = (i0 >= 128) ? (i0 - 128) : 0;
    const int Wn   = i0 + 128 - j0;           // 128 or 256
    const int qoff = i0 - j0;                 // 0 or 128
    const int nstr = (i0 >= 256) ? (i0 / 128 - 1) : 0;

    const int tid = threadIdx.x;

    // ---- Q window -> smem, tf32-rounded; mask row -> smem ----
    for (int idx = tid; idx < Wn * 16; idx += 256) {
        int r = idx >> 4, c = (idx & 15) * 4;
        *(uint4*)&QV[r * QPITCH + c] =
            rna4(*(const float4*)&Qg[(size_t)(j0 + r) * HDIM + c]);
    }
    for (int idx = tid; idx < Wn; idx += 256) ams[idx] = amb[j0 + idx];
    __syncthreads();

    const int wid = tid >> 5, lane = tid & 31;
    const int g  = lane >> 2, lq = lane & 3;
    const int r0 = wid * 16;
    const int t_lo = (qoff + r0 - 128) >> 3;
    const int rowA = qoff + r0 + g;           // query rows rowA, rowA+8 (window idx)

    // ---- S = Q_tile . Q_win^T over live band ----
    float acc[NT_S][4];
#pragma unroll
    for (int u = 0; u < NT_S; u++)
#pragma unroll
        for (int e = 0; e < 4; e++) acc[u][e] = 0.f;

    const float* Qs = QV;
#pragma unroll
    for (int kd = 0; kd < 8; kd++) {
        const int k = kd * 8 + lq;
        uint32_t a0 = __float_as_uint(Qs[rowA * QPITCH + k]);
        uint32_t a1 = __float_as_uint(Qs[(rowA + 8) * QPITCH + k]);
        uint32_t a2 = __float_as_uint(Qs[rowA * QPITCH + k + 4]);
        uint32_t a3 = __float_as_uint(Qs[(rowA + 8) * QPITCH + k + 4]);
#pragma unroll
        for (int u = 0; u < NT_S; u++) {
            const int t = t_lo + u;
            if (t >= 0) {
                const int kr = t * 8 + g;
                uint32_t b0 = __float_as_uint(Qs[kr * QPITCH + k]);
                uint32_t b1 = __float_as_uint(Qs[kr * QPITCH + k + 4]);
                MMA_TF32(acc[u], a0, a1, a2, a3, b0, b1);
            }
        }
    }

    // ---- pass 1: scale + am, row max (allowed: diff in [0,128]) ----
    float mx0 = -1e30f, mx1 = -1e30f;
#pragma unroll
    for (int u = 0; u < NT_S; u++) {
        const int t = t_lo + u;
        if (t >= 0) {
            const int c = t * 8 + 2 * lq;
            const float a0 = ams[c], a1 = ams[c + 1];
            const int d0 = rowA - c;          // row0 diff at col c
            const int d1 = d0 + 8;            // row1 diff at col c
            float s00 = acc[u][0] * 0.125f + a0;
            float s01 = acc[u][1] * 0.125f + a1;
            float s10 = acc[u][2] * 0.125f + a0;
            float s11 = acc[u][3] * 0.125f + a1;
            acc[u][0] = s00; acc[u][1] = s01; acc[u][2] = s10; acc[u][3] = s11;
            if (d0 >= 0 && d0 <= 128)         mx0 = fmaxf(mx0, s00);
            if (d0 >= 1 && d0 <= 129)         mx0 = fmaxf(mx0, s01);
            if (d1 >= 0 && d1 <= 128)         mx1 = fmaxf(mx1, s10);
            if (d1 >= 1 && d1 <= 129)         mx1 = fmaxf(mx1, s11);
        }
    }

    // ---- strided scores (scalar; keys k = lq + 4u) ----
    float ss0[4], ss1[4];
#pragma unroll
    for (int u = 0; u < 4; u++) {
        const int k = lq + u * 4;
        float s0 = -1e30f, s1 = -1e30f;
        if (k < nstr) {
            const int jb0 = (r0 + g) + 128 * k;
            const float4* q0 = (const float4*)&Qs[rowA * QPITCH];
            const float4* q1 = (const float4*)&Qs[(rowA + 8) * QPITCH];
            const float4* k0 = (const float4*)&Qg[(size_t)jb0 * HDIM];
            const float4* k1 = (const float4*)&Qg[(size_t)(jb0 + 8) * HDIM];
            float d0 = 0.f, d1 = 0.f;
#pragma unroll
            for (int it = 0; it < 16; it++) {
                float4 qa = q0[it], kb = k0[it];
                d0 += qa.x * kb.x + qa.y * kb.y + qa.z * kb.z + qa.w * kb.w;
                float4 qb = q1[it], kc = k1[it];
                d1 += qb.x * kc.x + qb.y * kc.y + qb.z * kc.z + qb.w * kc.w;
            }
            s0 = d0 * 0.125f + amb[jb0];
            s1 = d1 * 0.125f + amb[jb0 + 8];
            mx0 = fmaxf(mx0, s0);
            mx1 = fmaxf(mx1, s1);
        }
        ss0[u] = s0; ss1[u] = s1;
    }

    mx0 = fmaxf(mx0, __shfl_xor_sync(0xFFFFFFFFu, mx0, 1));
    mx0 = fmaxf(mx0, __shfl_xor_sync(0xFFFFFFFFu, mx0, 2));
    mx1 = fmaxf(mx1, __shfl_xor_sync(0xFFFFFFFFu, mx1, 1));
    mx1 = fmaxf(mx1, __shfl_xor_sync(0xFFFFFFFFu, mx1, 2));

    // ---- pass 2: exp, sum, write p (tf32) ----
    float sum0 = 0.f, sum1 = 0.f;
#pragma unroll
    for (int u = 0; u < NT_S; u++) {
        const int t = t_lo + u;
        if (t >= 0) {
            const int c = t * 8 + 2 * lq;
            const int d0 = rowA - c;
            const int d1 = d0 + 8;
            float p00 = (d0 >= 0 && d0 <= 128) ? __expf(acc[u][0] - mx0) : 0.f;
            float p01 = (d0 >= 1 && d0 <= 129) ? __expf(acc[u][1] - mx0) : 0.f;
            float p10 = (d1 >= 0 && d1 <= 128) ? __expf(acc[u][2] - mx1) : 0.f;
            float p11 = (d1 >= 1 && d1 <= 129) ? __expf(acc[u][3] - mx1) : 0.f;
            sum0 += p00 + p01;
            sum1 += p10 + p11;
            uint2 w0 = {rna1(p00), rna1(p01)};
            uint2 w1 = {rna1(p10), rna1(p11)};
            *(uint2*)&P[(r0 + g) * PPITCH3 + c]     = w0;
            *(uint2*)&P[(r0 + g + 8) * PPITCH3 + c] = w1;
        }
    }
#pragma unroll
    for (int u = 0; u < 4; u++) {
        const int k = lq + u * 4;
        if (k < nstr) {
            float p0 = __expf(ss0[u] - mx0);
            float p1 = __expf(ss1[u] - mx1);
            sum0 += p0; sum1 += p1;
            sstr[k * 128 + r0 + g]     = p0;
            sstr[k * 128 + r0 + g + 8] = p1;
        }
    }
    sum0 += __shfl_xor_sync(0xFFFFFFFFu, sum0, 1);
    sum0 += __shfl_xor_sync(0xFFFFFFFFu, sum0, 2);
    sum1 += __shfl_xor_sync(0xFFFFFFFFu, sum1, 1);
    sum1 += __shfl_xor_sync(0xFFFFFFFFu, sum1, 2);
    const float inv0 = 1.0f / sum0;
    const float inv1 = 1.0f / sum1;

    __syncthreads();                           // all warps done reading Qs

    // ---- V window -> smem (tf32), pitch 72 ----
    for (int idx = tid; idx < Wn * 16; idx += 256) {
        int r = idx >> 4, c = (idx & 15) * 4;
        *(uint4*)&QV[r * VPITCH3 + c] =
            rna4(*(const float4*)&Vg[(size_t)(j0 + r) * HDIM + c]);
    }
    __syncthreads();

    // ---- PV over live band ----
    float oacc[8][4];
#pragma unroll
    for (int nt = 0; nt < 8; nt++)
#pragma unroll
        for (int e = 0; e < 4; e++) oacc[nt][e] = 0.f;

#pragma unroll
    for (int u = 0; u < NT_S; u++) {
        const int t = t_lo + u;
        if (t >= 0) {
            const int kb = t * 8;
            uint32_t a0 = __float_as_uint(P[(r0 + g) * PPITCH3 + kb + lq]);
            uint32_t a1 = __float_as_uint(P[(r0 + g + 8) * PPITCH3 + kb + lq]);
            uint32_t a2 = __float_as_uint(P[(r0 + g) * PPITCH3 + kb + lq + 4]);
            uint32_t a3 = __float_as_uint(P[(r0 + g + 8) * PPITCH3 + kb + lq + 4]);
#pragma unroll
            for (int nt = 0; nt < 8; nt++) {
                uint32_t b0 = __float_as_uint(QV[(kb + lq) * VPITCH3 + nt * 8 + g]);
                uint32_t b1 = __float_as_uint(QV[(kb + lq + 4) * VPITCH3 + nt * 8 + g]);
                MMA_TF32(oacc[nt], a0, a1, a2, a3, b0, b1);
            }
        }
    }

    // ---- strided PV (scalar, V from global fp32) ----
    for (int k = 0; k < nstr; k++) {
        const float p0 = sstr[k * 128 + r0 + g];
        const float p1 = sstr[k * 128 + r0 + g + 8];
        const float* v0 = &Vg[(size_t)((r0 + g) + 128 * k) * HDIM];
        const float* v1 = v0 + 8 * HDIM;
#pragma unroll
        for (int nt = 0; nt < 8; nt++) {
            float2 x0 = *(const float2*)&v0[nt * 8 + 2 * lq];
            float2 x1 = *(const float2*)&v1[nt * 8 + 2 * lq];
            oacc[nt][0] += p0 * x0.x; oacc[nt][1] += p0 * x0.y;
            oacc[nt][2] += p1 * x1.x; oacc[nt][3] += p1 * x1.y;
        }
    }

    // ---- epilogue ----
    const int iA = i0 + r0 + g;
    float* oA = &out[((size_t)(b * S_LEN + iA)) * HID + h * HDIM];
    float* oB = oA + 8 * HID;
#pragma unroll
    for (int nt = 0; nt < 8; nt++) {
        const int n = nt * 8 + 2 * lq;
        float2 w0 = {oacc[nt][0] * inv0, oacc[nt][1] * inv0};
        float2 w1 = {oacc[nt][2] * inv1, oacc[nt][3] * inv1};
        *(float2*)&oA[n] = w0;
        *(float2*)&oB[n] = w1;
    }
}

// ---------------------------------------------------------------------------
extern "C" void kernel_launch(void* const* d_in, const int* in_sizes, int n_in,
                              void* d_out, int out_size)
{
    const float* hidden = (const float*)d_in[0];
    const float* am     = (const float*)d_in[1];
    const float* Wq     = (const float*)d_in[2];
    const float* bq     = (const float*)d_in[3];
    const float* Wv     = (const float*)d_in[4];
    const float* bv     = (const float*)d_in[5];
    float* out = (float*)d_out;

    (void)in_sizes; (void)n_in; (void)out_size;

    cudaFuncSetAttribute(proj_mma,
                         cudaFuncAttributeMaxDynamicSharedMemorySize, PROJ_SMEM);
    cudaFuncSetAttribute(attn_mma,
                         cudaFuncAttributeMaxDynamicSharedMemorySize, ATTN3_SMEM);

    conv_A_tf32<<<(M_ROWS * HID / 4) / 256, 256>>>(hidden);
    dim3 gw((HID * HID / 4) / 256, 2);
    conv_W_tf32<<<gw, 256>>>(Wq, Wv);

    dim3 gp(HID / 128, M_ROWS / 128, 2);
    proj_mma<<<gp, 256, PROJ_SMEM>>>(bq, bv);

    dim3 ga(S_LEN / 128, BH);
    attn_mma<<<ga, 256, ATTN3_SMEM>>>(am, out);
}

// round 7
// speedup vs baseline: 5.8858x; 1.1234x over previous
#include <cuda_runtime.h>
#include <cstdint>

#define S_LEN   2048
#define HID     1024
#define NHEAD   16
#define HDIM    64
#define NBATCH  2
#define M_ROWS  (NBATCH * S_LEN)      // 4096
#define BH      (NBATCH * NHEAD)      // 32

// Scratch (device globals; ONLY referenced from device code)
__device__ float g_Q[(size_t)BH * S_LEN * HDIM];
__device__ float g_V[(size_t)BH * S_LEN * HDIM];
__device__ float g_At[(size_t)M_ROWS * HID];        // tf32-rounded hidden
__device__ float g_Wt[2 * (size_t)HID * HID];       // tf32-rounded Wq, Wv

// ---------------------------------------------------------------------------
// tf32 helpers
// ---------------------------------------------------------------------------
__device__ __forceinline__ uint4 rna4(float4 v) {
    uint4 u;
    asm("cvt.rna.tf32.f32 %0, %1;" : "=r"(u.x) : "f"(v.x));
    asm("cvt.rna.tf32.f32 %0, %1;" : "=r"(u.y) : "f"(v.y));
    asm("cvt.rna.tf32.f32 %0, %1;" : "=r"(u.z) : "f"(v.z));
    asm("cvt.rna.tf32.f32 %0, %1;" : "=r"(u.w) : "f"(v.w));
    return u;
}
__device__ __forceinline__ uint32_t rna1(float v) {
    uint32_t u;
    asm("cvt.rna.tf32.f32 %0, %1;" : "=r"(u) : "f"(v));
    return u;
}

__global__ void conv_A_tf32(const float* __restrict__ src)
{
    size_t i = (size_t)blockIdx.x * blockDim.x + threadIdx.x;
    ((uint4*)g_At)[i] = rna4(((const float4*)src)[i]);
}

__global__ void conv_W_tf32(const float* __restrict__ Wq,
                            const float* __restrict__ Wv)
{
    const int z = blockIdx.y;
    const float* src = z ? Wv : Wq;
    float* dst = g_Wt + (size_t)z * HID * HID;
    size_t i = (size_t)blockIdx.x * blockDim.x + threadIdx.x;
    ((uint4*)dst)[i] = rna4(((const float4*)src)[i]);
}

// ---------------------------------------------------------------------------
// tf32 mma.sync projection GEMM (unchanged; near legacy-HMMA ceiling)
// ---------------------------------------------------------------------------
#define BKG 32
#define APITCH 36
#define BPITCH 136
#define ABUF (128 * APITCH)
#define BBUF (32 * BPITCH)
#define PROJ_SMEM ((2 * ABUF + 2 * BBUF) * 4)       // 71680 B

__device__ __forceinline__ uint32_t smem_u32(const void* p) {
    uint32_t a;
    asm("{ .reg .u64 t; cvta.to.shared.u64 t, %1; cvt.u32.u64 %0, t; }"
        : "=r"(a) : "l"(p));
    return a;
}

#define CP16(dst, src) \
    asm volatile("cp.async.cg.shared.global [%0], [%1], 16;" \
                 :: "r"(dst), "l"(src) : "memory")
#define CP_COMMIT() asm volatile("cp.async.commit_group;" ::: "memory")
#define CP_WAIT1()  asm volatile("cp.async.wait_group 1;" ::: "memory")
#define CP_WAIT0()  asm volatile("cp.async.wait_group 0;" ::: "memory")

#define MMA_TF32(c, a0, a1, a2, a3, b0, b1)                                   \
    asm volatile("mma.sync.aligned.m16n8k8.row.col.f32.tf32.tf32.f32 "        \
        "{%0,%1,%2,%3}, {%4,%5,%6,%7}, {%8,%9}, {%0,%1,%2,%3};"               \
        : "+f"((c)[0]), "+f"((c)[1]), "+f"((c)[2]), "+f"((c)[3])              \
        : "r"(a0), "r"(a1), "r"(a2), "r"(a3), "r"(b0), "r"(b1))

__global__ __launch_bounds__(256)
void proj_mma(const float* __restrict__ bq, const float* __restrict__ bv)
{
    extern __shared__ float smp[];
    float* Asm = smp;                       // [2][128][APITCH]
    float* Bsm = smp + 2 * ABUF;            // [2][32][BPITCH]

    const int tid = threadIdx.x;
    const int z  = blockIdx.z;
    const int n0 = blockIdx.x * 128;
    const int m0 = blockIdx.y * 128;

    const float* Wg   = g_Wt + (size_t)z * HID * HID;
    const float* bias = z ? bv : bq;
    float*       Out  = z ? g_V : g_Q;

    const uint32_t sA = smem_u32(Asm);
    const uint32_t sB = smem_u32(Bsm);

    auto load_stage = [&](int s, int buf) {
        const int k0 = s * BKG;
        const uint32_t aB = sA + buf * ABUF * 4;
        const uint32_t bB = sB + buf * BBUF * 4;
#pragma unroll
        for (int it = 0; it < 4; it++) {
            int idx = tid + it * 256;
            int r = idx >> 3, c = idx & 7;
            CP16(aB + (r * APITCH + c * 4) * 4,
                 &g_At[(size_t)(m0 + r) * HID + k0 + c * 4]);
        }
#pragma unroll
        for (int it = 0; it < 4; it++) {
            int idx = tid + it * 256;
            int k = idx >> 5, c = idx & 31;
            CP16(bB + (k * BPITCH + c * 4) * 4,
                 &Wg[(size_t)(k0 + k) * HID + n0 + c * 4]);
        }
        CP_COMMIT();
    };

    const int wid = tid >> 5, lane = tid & 31;
    const int wm = (wid & 1) * 64;
    const int wn = (wid >> 1) * 32;
    const int lg = lane >> 2, lq = lane & 3;

    float acc[4][4][4];
#pragma unroll
    for (int mt = 0; mt < 4; mt++)
#pragma unroll
        for (int nt = 0; nt < 4; nt++)
#pragma unroll
            for (int e = 0; e < 4; e++) acc[mt][nt][e] = 0.f;

    auto compute_stage = [&](int buf) {
        const float* Ab = Asm + buf * ABUF;
        const float* Bb = Bsm + buf * BBUF;
#pragma unroll
        for (int ks = 0; ks < 4; ks++) {
            const int kb = ks * 8;
            uint32_t b0[4], b1[4];
#pragma unroll
            for (int nt = 0; nt < 4; nt++) {
                const int n = wn + nt * 8 + lg;
                b0[nt] = __float_as_uint(Bb[(kb + lq) * BPITCH + n]);
                b1[nt] = __float_as_uint(Bb[(kb + lq + 4) * BPITCH + n]);
            }
#pragma unroll
            for (int mt = 0; mt < 4; mt++) {
                const float* ar = Ab + (wm + mt * 16 + lg) * APITCH + kb + lq;
                uint32_t a0 = __float_as_uint(ar[0]);
                uint32_t a1 = __float_as_uint(ar[8 * APITCH]);
                uint32_t a2 = __float_as_uint(ar[4]);
                uint32_t a3 = __float_as_uint(ar[8 * APITCH + 4]);
#pragma unroll
                for (int nt = 0; nt < 4; nt++)
                    MMA_TF32(acc[mt][nt], a0, a1, a2, a3, b0[nt], b1[nt]);
            }
        }
    };

    load_stage(0, 0);
    load_stage(1, 1);
    const int NST = HID / BKG;              // 32
    for (int s = 0; s < NST; s++) {
        if (s < NST - 1) CP_WAIT1(); else CP_WAIT0();
        __syncthreads();
        compute_stage(s & 1);
        __syncthreads();
        if (s + 2 < NST) load_stage(s + 2, s & 1);
    }

#pragma unroll
    for (int mt = 0; mt < 4; mt++) {
        const int mA = m0 + wm + mt * 16 + lg;
        const int mB = mA + 8;
#pragma unroll
        for (int nt = 0; nt < 4; nt++) {
            const int n = n0 + wn + nt * 8 + lq * 2;
            const float2 b2 = *(const float2*)&bias[n];
            const int h = n >> 6, d = n & 63;
            {
                int bb = mA >> 11, sr = mA & (S_LEN - 1);
                float2 o = {acc[mt][nt][0] + b2.x, acc[mt][nt][1] + b2.y};
                *(float2*)&Out[((size_t)((bb * NHEAD + h) * S_LEN + sr)) * HDIM + d] = o;
            }
            {
                int bb = mB >> 11, sr = mB & (S_LEN - 1);
                float2 o = {acc[mt][nt][2] + b2.x, acc[mt][nt][3] + b2.y};
                *(float2*)&Out[((size_t)((bb * NHEAD + h) * S_LEN + sr)) * HDIM + d] = o;
            }
        }
    }
}

// ---------------------------------------------------------------------------
// Attention v4: tf32 mma, 512 threads / 16 warps, warp-pair work split.
// Row group j (16 queries) handled by warps 2j (hb=0) and 2j+1 (hb=1).
//   S phase:  hb splits the 18 band n8-tiles -> 9 tiles/warp, acc[9][4].
//             Raw scaled scores + am -> P smem (fp32).
//   Softmax:  4 lanes per row (tid>>2), mask->exact 0, p -> tf32 in P,
//             1/sum -> smem.
//   PV phase: hb splits the 64 output dims -> 4 n8-tiles/warp over all 18
//             k-tiles, oacc[4][4]; disjoint output columns, no combine.
// Strided diagonal keys handled scalar in softmax/PV phases.
// ---------------------------------------------------------------------------
#define QPITCH 68
#define VPITCH3 72
#define PPITCH3 260
#define QV3_FLOATS (256 * VPITCH3)          // 18432
#define ATTN3_FLOATS (128 * PPITCH3 + QV3_FLOATS + 256 + 15 * 128 + 128)
#define ATTN3_SMEM (ATTN3_FLOATS * 4)       // 216064 B

__global__ __launch_bounds__(512, 1)
void attn_mma(const float* __restrict__ am, float* __restrict__ out)
{
    extern __shared__ float sm3[];
    float* P    = sm3;                        // [128][260]
    float* QV   = sm3 + 128 * PPITCH3;        // Qs[256][68] then Vs[256][72]
    float* ams  = QV + QV3_FLOATS;            // [256]
    float* sstr = ams + 256;                  // [15][128]
    float* sinv = sstr + 15 * 128;            // [128]

    const int i0 = blockIdx.x * 128;
    const int bh = blockIdx.y;
    const int b  = bh >> 4;
    const int h  = bh & 15;

    const float* Qg  = g_Q + (size_t)bh * S_LEN * HDIM;
    const float* Vg  = g_V + (size_t)bh * S_LEN * HDIM;
    const float* amb = am + (size_t)b * S_LEN;

    const int j0   = (i0 >= 128) ? (i0 - 128) : 0;
    const int Wn   = i0 + 128 - j0;           // 128 or 256
    const int qoff = i0 - j0;                 // 0 or 128
    const int nstr = (i0 >= 256) ? (i0 / 128 - 1) : 0;

    const int tid = threadIdx.x;

    // ---- Q window -> smem (tf32), pitch 68; mask row -> smem ----
    for (int idx = tid; idx < Wn * 16; idx += 512) {
        int r = idx >> 4, c = (idx & 15) * 4;
        *(uint4*)&QV[r * QPITCH + c] =
            rna4(*(const float4*)&Qg[(size_t)(j0 + r) * HDIM + c]);
    }
    for (int idx = tid; idx < Wn; idx += 512) ams[idx] = amb[j0 + idx];
    __syncthreads();

    const int wid = tid >> 5, lane = tid & 31;
    const int g  = lane >> 2, lq = lane & 3;
    const int jgrp = wid >> 1, hb = wid & 1;
    const int r0 = jgrp * 16;
    const int t_lo = (qoff + r0 - 128) >> 3;
    const int rowA = qoff + r0 + g;

    const float* Qs = QV;

    // ---- phase A: S band (9 tiles per warp) -> raw scores to P ----
    {
        float acc[9][4];
#pragma unroll
        for (int u = 0; u < 9; u++)
#pragma unroll
            for (int e = 0; e < 4; e++) acc[u][e] = 0.f;

#pragma unroll
        for (int kd = 0; kd < 8; kd++) {
            const int k = kd * 8 + lq;
            uint32_t a0 = __float_as_uint(Qs[rowA * QPITCH + k]);
            uint32_t a1 = __float_as_uint(Qs[(rowA + 8) * QPITCH + k]);
            uint32_t a2 = __float_as_uint(Qs[rowA * QPITCH + k + 4]);
            uint32_t a3 = __float_as_uint(Qs[(rowA + 8) * QPITCH + k + 4]);
#pragma unroll
            for (int u = 0; u < 9; u++) {
                const int t = t_lo + hb * 9 + u;
                if (t >= 0) {
                    const int kr = t * 8 + g;
                    uint32_t b0 = __float_as_uint(Qs[kr * QPITCH + k]);
                    uint32_t b1 = __float_as_uint(Qs[kr * QPITCH + k + 4]);
                    MMA_TF32(acc[u], a0, a1, a2, a3, b0, b1);
                }
            }
        }
#pragma unroll
        for (int u = 0; u < 9; u++) {
            const int t = t_lo + hb * 9 + u;
            if (t >= 0) {
                const int c = t * 8 + 2 * lq;
                const float a0m = ams[c], a1m = ams[c + 1];
                float2 w0 = {acc[u][0] * 0.125f + a0m, acc[u][1] * 0.125f + a1m};
                float2 w1 = {acc[u][2] * 0.125f + a0m, acc[u][3] * 0.125f + a1m};
                *(float2*)&P[(r0 + g) * PPITCH3 + c]     = w0;
                *(float2*)&P[(r0 + g + 8) * PPITCH3 + c] = w1;
            }
        }
    }

    // ---- phase B: strided scores (4 lanes per row) ----
    const int rB = tid >> 2;
    const int qB = tid & 3;
    {
        const float4* qp = (const float4*)&Qs[(qoff + rB) * QPITCH + qB * 16];
        for (int k = 0; k < nstr; k++) {
            const int jb = rB + 128 * k;
            const float4* kp = (const float4*)&Qg[(size_t)jb * HDIM + qB * 16];
            float s = 0.f;
#pragma unroll
            for (int it = 0; it < 4; it++) {
                float4 qa = qp[it], kb4 = kp[it];
                s += qa.x * kb4.x + qa.y * kb4.y + qa.z * kb4.z + qa.w * kb4.w;
            }
            s += __shfl_xor_sync(0xFFFFFFFFu, s, 1);
            s += __shfl_xor_sync(0xFFFFFFFFu, s, 2);
            if (qB == 0) sstr[k * 128 + rB] = s * 0.125f + amb[jb];
        }
    }
    __syncthreads();

    // ---- phase C: softmax (p -> tf32 in P, masked -> exact 0) ----
    {
        const int r   = rB;
        const int clo = max(0, qoff + r - 128);
        const int chi = qoff + r;
        float* Pr = &P[r * PPITCH3];

        float mx = -1e30f;
        for (int c = clo + qB; c <= chi; c += 4) mx = fmaxf(mx, Pr[c]);
        for (int k = qB; k < nstr; k += 4)       mx = fmaxf(mx, sstr[k * 128 + r]);
        mx = fmaxf(mx, __shfl_xor_sync(0xFFFFFFFFu, mx, 1));
        mx = fmaxf(mx, __shfl_xor_sync(0xFFFFFFFFu, mx, 2));

        const int tl  = (qoff + (r & ~15) - 128) >> 3;
        const int wlo = max(tl, 0) * 8;
        const int whi = (tl + 18) * 8;

        float sum = 0.f;
        for (int c = wlo + qB; c < whi; c += 4) {
            float v = Pr[c];
            float p = (c >= clo && c <= chi) ? __expf(v - mx) : 0.f;
            Pr[c] = __uint_as_float(rna1(p));
            sum += p;
        }
        for (int k = qB; k < nstr; k += 4) {
            float p = __expf(sstr[k * 128 + r] - mx);
            sstr[k * 128 + r] = p;
            sum += p;
        }
        sum += __shfl_xor_sync(0xFFFFFFFFu, sum, 1);
        sum += __shfl_xor_sync(0xFFFFFFFFu, sum, 2);
        if (qB == 0) sinv[r] = 1.0f / sum;
    }

    // ---- V window -> smem (tf32), pitch 72 (overwrites Qs) ----
    for (int idx = tid; idx < Wn * 16; idx += 512) {
        int r = idx >> 4, c = (idx & 15) * 4;
        *(uint4*)&QV[r * VPITCH3 + c] =
            rna4(*(const float4*)&Vg[(size_t)(j0 + r) * HDIM + c]);
    }
    __syncthreads();

    // ---- phase D: PV (4 n8-tiles per warp over all 18 k-tiles) ----
    const float* Vs = QV;
    float oacc[4][4];
#pragma unroll
    for (int nt = 0; nt < 4; nt++)
#pragma unroll
        for (int e = 0; e < 4; e++) oacc[nt][e] = 0.f;

#pragma unroll
    for (int u = 0; u < 18; u++) {
        const int t = t_lo + u;
        if (t >= 0) {
            const int kb = t * 8;
            uint32_t a0 = __float_as_uint(P[(r0 + g) * PPITCH3 + kb + lq]);
            uint32_t a1 = __float_as_uint(P[(r0 + g + 8) * PPITCH3 + kb + lq]);
            uint32_t a2 = __float_as_uint(P[(r0 + g) * PPITCH3 + kb + lq + 4]);
            uint32_t a3 = __float_as_uint(P[(r0 + g + 8) * PPITCH3 + kb + lq + 4]);
#pragma unroll
            for (int nt = 0; nt < 4; nt++) {
                const int ncol = hb * 32 + nt * 8 + g;
                uint32_t b0 = __float_as_uint(Vs[(kb + lq) * VPITCH3 + ncol]);
                uint32_t b1 = __float_as_uint(Vs[(kb + lq + 4) * VPITCH3 + ncol]);
                MMA_TF32(oacc[nt], a0, a1, a2, a3, b0, b1);
            }
        }
    }

    // strided PV (scalar, V from global fp32; each warp its 32-col half)
    for (int k = 0; k < nstr; k++) {
        const float p0 = sstr[k * 128 + r0 + g];
        const float p1 = sstr[k * 128 + r0 + g + 8];
        const float* v0 = &Vg[(size_t)((r0 + g) + 128 * k) * HDIM];
        const float* v1 = v0 + 8 * HDIM;
#pragma unroll
        for (int nt = 0; nt < 4; nt++) {
            const int n = hb * 32 + nt * 8 + 2 * lq;
            float2 x0 = *(const float2*)&v0[n];
            float2 x1 = *(const float2*)&v1[n];
            oacc[nt][0] += p0 * x0.x; oacc[nt][1] += p0 * x0.y;
            oacc[nt][2] += p1 * x1.x; oacc[nt][3] += p1 * x1.y;
        }
    }

    // ---- epilogue ----
    const float inv0 = sinv[r0 + g];
    const float inv1 = sinv[r0 + g + 8];
    const int iA = i0 + r0 + g;
    float* oA = &out[((size_t)(b * S_LEN + iA)) * HID + h * HDIM + hb * 32];
    float* oB = oA + 8 * HID;
#pragma unroll
    for (int nt = 0; nt < 4; nt++) {
        const int n = nt * 8 + 2 * lq;
        float2 w0 = {oacc[nt][0] * inv0, oacc[nt][1] * inv0};
        float2 w1 = {oacc[nt][2] * inv1, oacc[nt][3] * inv1};
        *(float2*)&oA[n] = w0;
        *(float2*)&oB[n] = w1;
    }
}

// ---------------------------------------------------------------------------
extern "C" void kernel_launch(void* const* d_in, const int* in_sizes, int n_in,
                              void* d_out, int out_size)
{
    const float* hidden = (const float*)d_in[0];
    const float* am     = (const float*)d_in[1];
    const float* Wq     = (const float*)d_in[2];
    const float* bq     = (const float*)d_in[3];
    const float* Wv     = (const float*)d_in[4];
    const float* bv     = (const float*)d_in[5];
    float* out = (float*)d_out;

    (void)in_sizes; (void)n_in; (void)out_size;

    cudaFuncSetAttribute(proj_mma,
                         cudaFuncAttributeMaxDynamicSharedMemorySize, PROJ_SMEM);
    cudaFuncSetAttribute(attn_mma,
                         cudaFuncAttributeMaxDynamicSharedMemorySize, ATTN3_SMEM);

    conv_A_tf32<<<(M_ROWS * HID / 4) / 256, 256>>>(hidden);
    dim3 gw((HID * HID / 4) / 256, 2);
    conv_W_tf32<<<gw, 256>>>(Wq, Wv);

    dim3 gp(HID / 128, M_ROWS / 128, 2);
    proj_mma<<<gp, 256, PROJ_SMEM>>>(bq, bv);

    dim3 ga(S_LEN / 128, BH);
    attn_mma<<<ga, 512, ATTN3_SMEM>>>(am, out);
}

// round 8
// speedup vs baseline: 6.1404x; 1.0433x over previous
#include <cuda_runtime.h>
#include <cstdint>

#define S_LEN   2048
#define HID     1024
#define NHEAD   16
#define HDIM    64
#define NBATCH  2
#define M_ROWS  (NBATCH * S_LEN)      // 4096
#define BH      (NBATCH * NHEAD)      // 32

// Scratch (device globals; ONLY referenced from device code)
__device__ float g_Q[(size_t)BH * S_LEN * HDIM];
__device__ float g_V[(size_t)BH * S_LEN * HDIM];
__device__ float g_At[(size_t)M_ROWS * HID];        // tf32-rounded hidden
__device__ float g_Wt[2 * (size_t)HID * HID];       // tf32-rounded Wq, Wv

// ---------------------------------------------------------------------------
// tf32 helpers
// ---------------------------------------------------------------------------
__device__ __forceinline__ uint4 rna4(float4 v) {
    uint4 u;
    asm("cvt.rna.tf32.f32 %0, %1;" : "=r"(u.x) : "f"(v.x));
    asm("cvt.rna.tf32.f32 %0, %1;" : "=r"(u.y) : "f"(v.y));
    asm("cvt.rna.tf32.f32 %0, %1;" : "=r"(u.z) : "f"(v.z));
    asm("cvt.rna.tf32.f32 %0, %1;" : "=r"(u.w) : "f"(v.w));
    return u;
}
__device__ __forceinline__ uint32_t rna1(float v) {
    uint32_t u;
    asm("cvt.rna.tf32.f32 %0, %1;" : "=r"(u) : "f"(v));
    return u;
}

__global__ void conv_A_tf32(const float* __restrict__ src)
{
    size_t i = (size_t)blockIdx.x * blockDim.x + threadIdx.x;
    ((uint4*)g_At)[i] = rna4(((const float4*)src)[i]);
}

__global__ void conv_W_tf32(const float* __restrict__ Wq,
                            const float* __restrict__ Wv)
{
    const int z = blockIdx.y;
    const float* src = z ? Wv : Wq;
    float* dst = g_Wt + (size_t)z * HID * HID;
    size_t i = (size_t)blockIdx.x * blockDim.x + threadIdx.x;
    ((uint4*)dst)[i] = rna4(((const float4*)src)[i]);
}

// ---------------------------------------------------------------------------
// tf32 mma.sync projection GEMM (unchanged; at legacy tf32 mma rt=8 ceiling)
// ---------------------------------------------------------------------------
#define BKG 32
#define APITCH 36
#define BPITCH 136
#define ABUF (128 * APITCH)
#define BBUF (32 * BPITCH)
#define PROJ_SMEM ((2 * ABUF + 2 * BBUF) * 4)       // 71680 B

__device__ __forceinline__ uint32_t smem_u32(const void* p) {
    uint32_t a;
    asm("{ .reg .u64 t; cvta.to.shared.u64 t, %1; cvt.u32.u64 %0, t; }"
        : "=r"(a) : "l"(p));
    return a;
}

#define CP16(dst, src) \
    asm volatile("cp.async.cg.shared.global [%0], [%1], 16;" \
                 :: "r"(dst), "l"(src) : "memory")
#define CP_COMMIT() asm volatile("cp.async.commit_group;" ::: "memory")
#define CP_WAIT1()  asm volatile("cp.async.wait_group 1;" ::: "memory")
#define CP_WAIT0()  asm volatile("cp.async.wait_group 0;" ::: "memory")

#define MMA_TF32(c, a0, a1, a2, a3, b0, b1)                                   \
    asm volatile("mma.sync.aligned.m16n8k8.row.col.f32.tf32.tf32.f32 "        \
        "{%0,%1,%2,%3}, {%4,%5,%6,%7}, {%8,%9}, {%0,%1,%2,%3};"               \
        : "+f"((c)[0]), "+f"((c)[1]), "+f"((c)[2]), "+f"((c)[3])              \
        : "r"(a0), "r"(a1), "r"(a2), "r"(a3), "r"(b0), "r"(b1))

__global__ __launch_bounds__(256)
void proj_mma(const float* __restrict__ bq, const float* __restrict__ bv)
{
    extern __shared__ float smp[];
    float* Asm = smp;                       // [2][128][APITCH]
    float* Bsm = smp + 2 * ABUF;            // [2][32][BPITCH]

    const int tid = threadIdx.x;
    const int z  = blockIdx.z;
    const int n0 = blockIdx.x * 128;
    const int m0 = blockIdx.y * 128;

    const float* Wg   = g_Wt + (size_t)z * HID * HID;
    const float* bias = z ? bv : bq;
    float*       Out  = z ? g_V : g_Q;

    const uint32_t sA = smem_u32(Asm);
    const uint32_t sB = smem_u32(Bsm);

    auto load_stage = [&](int s, int buf) {
        const int k0 = s * BKG;
        const uint32_t aB = sA + buf * ABUF * 4;
        const uint32_t bB = sB + buf * BBUF * 4;
#pragma unroll
        for (int it = 0; it < 4; it++) {
            int idx = tid + it * 256;
            int r = idx >> 3, c = idx & 7;
            CP16(aB + (r * APITCH + c * 4) * 4,
                 &g_At[(size_t)(m0 + r) * HID + k0 + c * 4]);
        }
#pragma unroll
        for (int it = 0; it < 4; it++) {
            int idx = tid + it * 256;
            int k = idx >> 5, c = idx & 31;
            CP16(bB + (k * BPITCH + c * 4) * 4,
                 &Wg[(size_t)(k0 + k) * HID + n0 + c * 4]);
        }
        CP_COMMIT();
    };

    const int wid = tid >> 5, lane = tid & 31;
    const int wm = (wid & 1) * 64;
    const int wn = (wid >> 1) * 32;
    const int lg = lane >> 2, lq = lane & 3;

    float acc[4][4][4];
#pragma unroll
    for (int mt = 0; mt < 4; mt++)
#pragma unroll
        for (int nt = 0; nt < 4; nt++)
#pragma unroll
            for (int e = 0; e < 4; e++) acc[mt][nt][e] = 0.f;

    auto compute_stage = [&](int buf) {
        const float* Ab = Asm + buf * ABUF;
        const float* Bb = Bsm + buf * BBUF;
#pragma unroll
        for (int ks = 0; ks < 4; ks++) {
            const int kb = ks * 8;
            uint32_t b0[4], b1[4];
#pragma unroll
            for (int nt = 0; nt < 4; nt++) {
                const int n = wn + nt * 8 + lg;
                b0[nt] = __float_as_uint(Bb[(kb + lq) * BPITCH + n]);
                b1[nt] = __float_as_uint(Bb[(kb + lq + 4) * BPITCH + n]);
            }
#pragma unroll
            for (int mt = 0; mt < 4; mt++) {
                const float* ar = Ab + (wm + mt * 16 + lg) * APITCH + kb + lq;
                uint32_t a0 = __float_as_uint(ar[0]);
                uint32_t a1 = __float_as_uint(ar[8 * APITCH]);
                uint32_t a2 = __float_as_uint(ar[4]);
                uint32_t a3 = __float_as_uint(ar[8 * APITCH + 4]);
#pragma unroll
                for (int nt = 0; nt < 4; nt++)
                    MMA_TF32(acc[mt][nt], a0, a1, a2, a3, b0[nt], b1[nt]);
            }
        }
    };

    load_stage(0, 0);
    load_stage(1, 1);
    const int NST = HID / BKG;              // 32
    for (int s = 0; s < NST; s++) {
        if (s < NST - 1) CP_WAIT1(); else CP_WAIT0();
        __syncthreads();
        compute_stage(s & 1);
        __syncthreads();
        if (s + 2 < NST) load_stage(s + 2, s & 1);
    }

#pragma unroll
    for (int mt = 0; mt < 4; mt++) {
        const int mA = m0 + wm + mt * 16 + lg;
        const int mB = mA + 8;
#pragma unroll
        for (int nt = 0; nt < 4; nt++) {
            const int n = n0 + wn + nt * 8 + lq * 2;
            const float2 b2 = *(const float2*)&bias[n];
            const int h = n >> 6, d = n & 63;
            {
                int bb = mA >> 11, sr = mA & (S_LEN - 1);
                float2 o = {acc[mt][nt][0] + b2.x, acc[mt][nt][1] + b2.y};
                *(float2*)&Out[((size_t)((bb * NHEAD + h) * S_LEN + sr)) * HDIM + d] = o;
            }
            {
                int bb = mB >> 11, sr = mB & (S_LEN - 1);
                float2 o = {acc[mt][nt][2] + b2.x, acc[mt][nt][3] + b2.y};
                *(float2*)&Out[((size_t)((bb * NHEAD + h) * S_LEN + sr)) * HDIM + d] = o;
            }
        }
    }
}

// ---------------------------------------------------------------------------
// Attention v5: 64-query CTAs, 512 threads, compact band P, 2 CTAs/SM.
// Window rows [j0, i0+64), Wn<=192, qoff=min(i0,128). 4 row groups of 16,
// 4 warps per group (sb=0..3): S splits 18 band tiles 5/5/4/4; PV splits the
// 64 output dims 16/warp. P stored compact per group: col u*8+c for band tile
// t = t_lo(group)+u, u in [0,18). Cols with t<0 are never read. Strided keys
// j=(i mod 128)+128k, k<nstr=max(0,i0/128-1) handled scalar (8 lanes/row).
// Smem 98KB -> 2 CTAs/SM.
// ---------------------------------------------------------------------------
#define QPITCH 68
#define VPITCH4 72
#define PPITCH4 148
#define QV4_FLOATS (192 * VPITCH4)          // 13824
#define ATTN4_FLOATS (64 * PPITCH4 + QV4_FLOATS + 192 + 15 * 64 + 64)
#define ATTN4_SMEM (ATTN4_FLOATS * 4)       // 98048 B

__global__ __launch_bounds__(512, 2)
void attn_mma(const float* __restrict__ am, float* __restrict__ out)
{
    extern __shared__ float sm3[];
    float* P    = sm3;                        // [64][148] compact band
    float* QV   = sm3 + 64 * PPITCH4;         // Qs[192][68] then Vs[192][72]
    float* ams  = QV + QV4_FLOATS;            // [192]
    float* sstr = ams + 192;                  // [15][64]
    float* sinv = sstr + 15 * 64;             // [64]

    const int i0 = blockIdx.x * 64;
    const int bh = blockIdx.y;
    const int b  = bh >> 4;
    const int h  = bh & 15;

    const float* Qg  = g_Q + (size_t)bh * S_LEN * HDIM;
    const float* Vg  = g_V + (size_t)bh * S_LEN * HDIM;
    const float* amb = am + (size_t)b * S_LEN;

    const int j0   = (i0 >= 128) ? (i0 - 128) : 0;
    const int Wn   = i0 + 64 - j0;            // 64,128,192
    const int qoff = i0 - j0;                 // min(i0,128)
    const int nstr = (i0 >= 256) ? (i0 / 128 - 1) : 0;
    const int base = i0 & 127;                // 0 or 64 (strided residue base)

    const int tid = threadIdx.x;

    // ---- Q window -> smem (tf32), pitch 68; mask row -> smem ----
    for (int idx = tid; idx < Wn * 16; idx += 512) {
        int r = idx >> 4, c = (idx & 15) * 4;
        *(uint4*)&QV[r * QPITCH + c] =
            rna4(*(const float4*)&Qg[(size_t)(j0 + r) * HDIM + c]);
    }
    for (int idx = tid; idx < Wn; idx += 512) ams[idx] = amb[j0 + idx];
    __syncthreads();

    const int wid = tid >> 5, lane = tid & 31;
    const int g  = lane >> 2, lq = lane & 3;
    const int jgrp = wid >> 2, sb = wid & 3;
    const int r0 = jgrp * 16;
    const int t_lo = (qoff + r0 - 128) >> 3;
    const int rowA = qoff + r0 + g;
    const int NTW   = (sb < 2) ? 5 : 4;
    const int ubase = (sb < 2) ? sb * 5 : 10 + (sb - 2) * 4;

    const float* Qs = QV;

    // ---- phase A: S band tiles (5/5/4/4 per warp) -> compact P ----
    {
        float acc[5][4];
#pragma unroll
        for (int u = 0; u < 5; u++)
#pragma unroll
            for (int e = 0; e < 4; e++) acc[u][e] = 0.f;

#pragma unroll
        for (int kd = 0; kd < 8; kd++) {
            const int k = kd * 8 + lq;
            uint32_t a0 = __float_as_uint(Qs[rowA * QPITCH + k]);
            uint32_t a1 = __float_as_uint(Qs[(rowA + 8) * QPITCH + k]);
            uint32_t a2 = __float_as_uint(Qs[rowA * QPITCH + k + 4]);
            uint32_t a3 = __float_as_uint(Qs[(rowA + 8) * QPITCH + k + 4]);
#pragma unroll
            for (int u = 0; u < 5; u++) {
                const int t = t_lo + ubase + u;
                if (u < NTW && t >= 0) {
                    const int kr = t * 8 + g;
                    uint32_t b0 = __float_as_uint(Qs[kr * QPITCH + k]);
                    uint32_t b1 = __float_as_uint(Qs[kr * QPITCH + k + 4]);
                    MMA_TF32(acc[u], a0, a1, a2, a3, b0, b1);
                }
            }
        }
#pragma unroll
        for (int u = 0; u < 5; u++) {
            const int t = t_lo + ubase + u;
            if (u < NTW && t >= 0) {
                const int cabs = t * 8 + 2 * lq;          // window col
                const int cc   = (ubase + u) * 8 + 2 * lq; // compact col
                const float a0m = ams[cabs], a1m = ams[cabs + 1];
                float2 w0 = {acc[u][0] * 0.125f + a0m, acc[u][1] * 0.125f + a1m};
                float2 w1 = {acc[u][2] * 0.125f + a0m, acc[u][3] * 0.125f + a1m};
                *(float2*)&P[(r0 + g) * PPITCH4 + cc]     = w0;
                *(float2*)&P[(r0 + g + 8) * PPITCH4 + cc] = w1;
            }
        }
    }

    // ---- phase B: strided scores (8 lanes per row) ----
    const int rB  = tid >> 3;                 // 0..63
    const int qB8 = tid & 7;                  // 0..7
    {
        const float4* qp = (const float4*)&Qs[(qoff + rB) * QPITCH + qB8 * 8];
        for (int k = 0; k < nstr; k++) {
            const int jb = base + rB + 128 * k;
            const float4* kp = (const float4*)&Qg[(size_t)jb * HDIM + qB8 * 8];
            float4 qa = qp[0], kb4 = kp[0];
            float s = qa.x * kb4.x + qa.y * kb4.y + qa.z * kb4.z + qa.w * kb4.w;
            float4 qb = qp[1], kc4 = kp[1];
            s += qb.x * kc4.x + qb.y * kc4.y + qb.z * kc4.z + qb.w * kc4.w;
            s += __shfl_xor_sync(0xFFFFFFFFu, s, 1);
            s += __shfl_xor_sync(0xFFFFFFFFu, s, 2);
            s += __shfl_xor_sync(0xFFFFFFFFu, s, 4);
            if (qB8 == 0) sstr[k * 64 + rB] = s * 0.125f + amb[jb];
        }
    }
    __syncthreads();

    // ---- phase C: softmax over compact band + strided ----
    {
        const int r   = rB;
        const int tlg = (qoff + (r & ~15) - 128) >> 3;
        const int off0 = max(0, qoff + r - 128) - tlg * 8;  // compact allowed lo
        const int off1 = (qoff + r) - tlg * 8;              // compact allowed hi
        const int vlo  = max(0, -tlg * 8);                  // first t>=0 col
        float* Pr = &P[r * PPITCH4];

        float mx = -1e30f;
        for (int c = off0 + ((qB8 - off0) & 7); c <= off1; c += 8)
            mx = fmaxf(mx, Pr[c]);
        for (int k = qB8; k < nstr; k += 8) mx = fmaxf(mx, sstr[k * 64 + r]);
        mx = fmaxf(mx, __shfl_xor_sync(0xFFFFFFFFu, mx, 1));
        mx = fmaxf(mx, __shfl_xor_sync(0xFFFFFFFFu, mx, 2));
        mx = fmaxf(mx, __shfl_xor_sync(0xFFFFFFFFu, mx, 4));

        float sum = 0.f;
        for (int c = vlo + ((qB8 - vlo) & 7); c < 144; c += 8) {
            float v = Pr[c];
            float p = (c >= off0 && c <= off1) ? __expf(v - mx) : 0.f;
            Pr[c] = __uint_as_float(rna1(p));
            sum += p;
        }
        for (int k = qB8; k < nstr; k += 8) {
            float p = __expf(sstr[k * 64 + r] - mx);
            sstr[k * 64 + r] = p;
            sum += p;
        }
        sum += __shfl_xor_sync(0xFFFFFFFFu, sum, 1);
        sum += __shfl_xor_sync(0xFFFFFFFFu, sum, 2);
        sum += __shfl_xor_sync(0xFFFFFFFFu, sum, 4);
        if (qB8 == 0) sinv[r] = 1.0f / sum;
    }

    // ---- V window -> smem (tf32), pitch 72 (overwrites Qs) ----
    for (int idx = tid; idx < Wn * 16; idx += 512) {
        int r = idx >> 4, c = (idx & 15) * 4;
        *(uint4*)&QV[r * VPITCH4 + c] =
            rna4(*(const float4*)&Vg[(size_t)(j0 + r) * HDIM + c]);
    }
    __syncthreads();

    // ---- phase D: PV (2 n8-tiles per warp over 18 compact k-tiles) ----
    const float* Vs = QV;
    float oacc[2][4];
#pragma unroll
    for (int nt = 0; nt < 2; nt++)
#pragma unroll
        for (int e = 0; e < 4; e++) oacc[nt][e] = 0.f;

#pragma unroll
    for (int u = 0; u < 18; u++) {
        const int t = t_lo + u;
        if (t >= 0) {
            const int cc = u * 8;                 // compact k base
            const int kb = t * 8;                 // window k base
            uint32_t a0 = __float_as_uint(P[(r0 + g) * PPITCH4 + cc + lq]);
            uint32_t a1 = __float_as_uint(P[(r0 + g + 8) * PPITCH4 + cc + lq]);
            uint32_t a2 = __float_as_uint(P[(r0 + g) * PPITCH4 + cc + lq + 4]);
            uint32_t a3 = __float_as_uint(P[(r0 + g + 8) * PPITCH4 + cc + lq + 4]);
#pragma unroll
            for (int nt = 0; nt < 2; nt++) {
                const int ncol = sb * 16 + nt * 8 + g;
                uint32_t b0 = __float_as_uint(Vs[(kb + lq) * VPITCH4 + ncol]);
                uint32_t b1 = __float_as_uint(Vs[(kb + lq + 4) * VPITCH4 + ncol]);
                MMA_TF32(oacc[nt], a0, a1, a2, a3, b0, b1);
            }
        }
    }

    // strided PV (scalar, V from global fp32; warp covers its 16 cols)
    for (int k = 0; k < nstr; k++) {
        const float p0 = sstr[k * 64 + r0 + g];
        const float p1 = sstr[k * 64 + r0 + g + 8];
        const float* v0 = &Vg[(size_t)(base + r0 + g + 128 * k) * HDIM];
        const float* v1 = v0 + 8 * HDIM;
#pragma unroll
        for (int nt = 0; nt < 2; nt++) {
            const int n = sb * 16 + nt * 8 + 2 * lq;
            float2 x0 = *(const float2*)&v0[n];
            float2 x1 = *(const float2*)&v1[n];
            oacc[nt][0] += p0 * x0.x; oacc[nt][1] += p0 * x0.y;
            oacc[nt][2] += p1 * x1.x; oacc[nt][3] += p1 * x1.y;
        }
    }

    // ---- epilogue ----
    const float inv0 = sinv[r0 + g];
    const float inv1 = sinv[r0 + g + 8];
    const int iA = i0 + r0 + g;
    float* oA = &out[((size_t)(b * S_LEN + iA)) * HID + h * HDIM + sb * 16];
    float* oB = oA + 8 * HID;
#pragma unroll
    for (int nt = 0; nt < 2; nt++) {
        const int n = nt * 8 + 2 * lq;
        float2 w0 = {oacc[nt][0] * inv0, oacc[nt][1] * inv0};
        float2 w1 = {oacc[nt][2] * inv1, oacc[nt][3] * inv1};
        *(float2*)&oA[n] = w0;
        *(float2*)&oB[n] = w1;
    }
}

// ---------------------------------------------------------------------------
extern "C" void kernel_launch(void* const* d_in, const int* in_sizes, int n_in,
                              void* d_out, int out_size)
{
    const float* hidden = (const float*)d_in[0];
    const float* am     = (const float*)d_in[1];
    const float* Wq     = (const float*)d_in[2];
    const float* bq     = (const float*)d_in[3];
    const float* Wv     = (const float*)d_in[4];
    const float* bv     = (const float*)d_in[5];
    float* out = (float*)d_out;

    (void)in_sizes; (void)n_in; (void)out_size;

    cudaFuncSetAttribute(proj_mma,
                         cudaFuncAttributeMaxDynamicSharedMemorySize, PROJ_SMEM);
    cudaFuncSetAttribute(attn_mma,
                         cudaFuncAttributeMaxDynamicSharedMemorySize, ATTN4_SMEM);

    conv_A_tf32<<<(M_ROWS * HID / 4) / 256, 256>>>(hidden);
    dim3 gw((HID * HID / 4) / 256, 2);
    conv_W_tf32<<<gw, 256>>>(Wq, Wv);

    dim3 gp(HID / 128, M_ROWS / 128, 2);
    proj_mma<<<gp, 256, PROJ_SMEM>>>(bq, bv);

    dim3 ga(S_LEN / 64, BH);
    attn_mma<<<ga, 512, ATTN4_SMEM>>>(am, out);
}